// round 4
// baseline (speedup 1.0000x reference)
#include <cuda_runtime.h>
#include <stdint.h>
#include <vector>
#include <algorithm>

#define NN 50000
#define EE 800000
#define FF 128
#define TSTEPS 5

// ---------------- static device buffers ----------------
__device__ int   g_ei[2 * EE];
__device__ int   g_cnt[NN];
__device__ int   g_rowptr[NN + 1];
__device__ int   g_cursor[NN];
__device__ int   g_csr[EE];
__device__ float g_dinv[NN];
__device__ float g_lin[(size_t)NN * 256];
__device__ float g_hbuf[(size_t)NN * 256];
__device__ float g_z[(size_t)NN * 128];
__device__ float g_Ut[(size_t)64 * NN];
__device__ float g_c[64];
__device__ unsigned long long g_amax[2];

struct FwdPlan { int i1[TSTEPS]; int i2[TSTEPS]; int coin[TSTEPS]; };

__device__ __forceinline__ unsigned long long packmax(float v, int idx) {
    unsigned u = __float_as_uint(v);
    u ^= ((unsigned)((int)u >> 31)) | 0x80000000u;
    return ((unsigned long long)u << 32) | (unsigned)(0xFFFFFFFFu - (unsigned)idx);
}
__device__ __forceinline__ int unpack_idx(unsigned long long k) {
    return (int)(0xFFFFFFFFu - (unsigned)(k & 0xFFFFFFFFu));
}
__device__ __forceinline__ void do_swap(int i1, int i2, int coin) {
    int a = g_ei[i1], b = g_ei[EE + i1];
    int c = g_ei[i2], d = g_ei[EE + i2];
    int n10, n11, n20, n21;
    if (coin) { n10 = a; n11 = d; n20 = c; n21 = b; }
    else      { n10 = a; n11 = c; n20 = b; n21 = d; }
    g_ei[i1] = n10; g_ei[EE + i1] = n11;
    g_ei[i2] = n20; g_ei[EE + i2] = n21;
}

// ---------------- graph structure ----------------
__global__ void copy_ei_kernel(const int* __restrict__ ei) {
    int i = blockIdx.x * blockDim.x + threadIdx.x;
    if (i < 2 * EE) g_ei[i] = ei[i];
    if (i == 0) g_amax[0] = 0ULL;
}
__global__ void zero_cnt_kernel() {
    int i = blockIdx.x * blockDim.x + threadIdx.x;
    if (i < NN) g_cnt[i] = 0;
}
__global__ void hist_kernel(const int* __restrict__ dst) {
    int e = blockIdx.x * blockDim.x + threadIdx.x;
    if (e < EE) atomicAdd(&g_cnt[dst[e]], 1);
}
__global__ void scan_kernel() {   // 1 block, 1024 threads
    __shared__ int part[1024];
    int tid = threadIdx.x;
    const int CHUNK = (NN + 1023) / 1024;
    int base = tid * CHUNK;
    int s = 0;
    for (int i = 0; i < CHUNK; i++) { int n = base + i; if (n < NN) s += g_cnt[n]; }
    part[tid] = s; __syncthreads();
    for (int off = 1; off < 1024; off <<= 1) {
        int v = (tid >= off) ? part[tid - off] : 0;
        __syncthreads();
        part[tid] += v;
        __syncthreads();
    }
    int run = (tid > 0) ? part[tid - 1] : 0;
    for (int i = 0; i < CHUNK; i++) {
        int n = base + i;
        if (n < NN) {
            g_rowptr[n] = run; g_cursor[n] = run;
            float df = (float)(g_cnt[n] + 1);
            float r = rsqrtf(df);
            r = r * (1.5f - 0.5f * df * r * r);
            g_dinv[n] = r;
            run += g_cnt[n];
        }
    }
    if (tid == 0) g_rowptr[NN] = part[1023];
}
__global__ void fill_kernel(const int* __restrict__ ei) {
    int e = blockIdx.x * blockDim.x + threadIdx.x;
    if (e < EE) {
        int s = ei[e], d = ei[EE + e];
        int pos = atomicAdd(&g_cursor[d], 1);
        g_csr[pos] = s;
    }
}

// ---------------- GEMM: out[m][c] = dinv[m]*(A[m]@W + Wd[K+deg[m]]) ----------------
template <int ONEHOT>
__global__ void __launch_bounds__(256) gemm_kernel(
    const float* __restrict__ A, int K, const float* __restrict__ W, int C,
    const int* __restrict__ deg, float* __restrict__ out) {
    __shared__ float As[16][128];
    __shared__ float Bs[16][128];
    const int M = NN;
    int bm = blockIdx.y * 128, bn = blockIdx.x * 128;
    int tid = threadIdx.x;
    int ty = tid >> 4, tx = tid & 15;
    float acc[8][8];
#pragma unroll
    for (int i = 0; i < 8; i++)
#pragma unroll
        for (int j = 0; j < 8; j++) acc[i][j] = 0.f;

    for (int k0 = 0; k0 < K; k0 += 16) {
#pragma unroll
        for (int it = 0; it < 2; it++) {
            int idx = tid + it * 256;
            int r = idx >> 2, c4 = (idx & 3) << 2;
            int gm = bm + r;
            float4 v = make_float4(0.f, 0.f, 0.f, 0.f);
            if (gm < M) v = *(const float4*)&A[(size_t)gm * K + k0 + c4];
            As[c4 + 0][r] = v.x; As[c4 + 1][r] = v.y;
            As[c4 + 2][r] = v.z; As[c4 + 3][r] = v.w;
        }
#pragma unroll
        for (int it = 0; it < 2; it++) {
            int idx = tid + it * 256;
            int r = idx >> 5, cc = (idx & 31) << 2;
            float4 v = *(const float4*)&W[(size_t)(k0 + r) * C + bn + cc];
            *(float4*)&Bs[r][cc] = v;
        }
        __syncthreads();
#pragma unroll
        for (int k = 0; k < 16; k++) {
            float a[8], b[8];
            *(float4*)&a[0] = *(const float4*)&As[k][ty * 8];
            *(float4*)&a[4] = *(const float4*)&As[k][ty * 8 + 4];
            *(float4*)&b[0] = *(const float4*)&Bs[k][tx * 8];
            *(float4*)&b[4] = *(const float4*)&Bs[k][tx * 8 + 4];
#pragma unroll
            for (int i = 0; i < 8; i++)
#pragma unroll
                for (int j = 0; j < 8; j++) acc[i][j] += a[i] * b[j];
        }
        __syncthreads();
    }
#pragma unroll
    for (int i = 0; i < 8; i++) {
        int m = bm + ty * 8 + i;
        if (m < M) {
            float dv = g_dinv[m];
            const float* wd = nullptr;
            if (ONEHOT) wd = W + (size_t)(K + deg[m]) * C + bn;
#pragma unroll
            for (int j = 0; j < 8; j++) {
                float v = acc[i][j];
                if (ONEHOT) v += wd[tx * 8 + j];
                out[(size_t)m * C + bn + tx * 8 + j] = v * dv;
            }
        }
    }
}

// ---------------- aggregation: out[n] = dinv[n]*(g[n] + sum_csr g[src]) + b ----------------
template <int C, int RELU>
__global__ void agg_kernel(const float* __restrict__ g, const float* __restrict__ bias,
                           float* __restrict__ out) {
    int warp = (blockIdx.x * blockDim.x + threadIdx.x) >> 5;
    int lane = threadIdx.x & 31;
    if (warp >= NN) return;
    int n = warp;
    const int V = C / 4;
    const float4* g4 = (const float4*)g;
    float4 a0 = g4[(size_t)n * V + lane];
    float4 a1 = make_float4(0.f, 0.f, 0.f, 0.f);
    if (C == 256) a1 = g4[(size_t)n * V + 32 + lane];
    int beg = g_rowptr[n], end = g_rowptr[n + 1];
    for (int p = beg; p < end; ++p) {
        int s = g_csr[p];
        float4 b0 = g4[(size_t)s * V + lane];
        a0.x += b0.x; a0.y += b0.y; a0.z += b0.z; a0.w += b0.w;
        if (C == 256) {
            float4 b1v = g4[(size_t)s * V + 32 + lane];
            a1.x += b1v.x; a1.y += b1v.y; a1.z += b1v.z; a1.w += b1v.w;
        }
    }
    float dv = g_dinv[n];
    const float4* bias4 = (const float4*)bias;
    float4 bb = bias4[lane];
    a0.x = a0.x * dv + bb.x; a0.y = a0.y * dv + bb.y;
    a0.z = a0.z * dv + bb.z; a0.w = a0.w * dv + bb.w;
    if (RELU) {
        a0.x = fmaxf(a0.x, 0.f); a0.y = fmaxf(a0.y, 0.f);
        a0.z = fmaxf(a0.z, 0.f); a0.w = fmaxf(a0.w, 0.f);
    }
    ((float4*)out)[(size_t)n * V + lane] = a0;
    if (C == 256) {
        float4 b2 = bias4[32 + lane];
        a1.x = a1.x * dv + b2.x; a1.y = a1.y * dv + b2.y;
        a1.z = a1.z * dv + b2.z; a1.w = a1.w * dv + b2.w;
        if (RELU) {
            a1.x = fmaxf(a1.x, 0.f); a1.y = fmaxf(a1.y, 0.f);
            a1.z = fmaxf(a1.z, 0.f); a1.w = fmaxf(a1.w, 0.f);
        }
        ((float4*)out)[(size_t)n * V + 32 + lane] = a1;
    }
}

// ---------------- edge predictors ----------------
__global__ void __launch_bounds__(64) u_kernel(const float* __restrict__ z,
                                               const float* __restrict__ w1) {
    __shared__ float ws[128 * 64];
    __shared__ float zs[8][128];
    int k = threadIdx.x;
    for (int i = k; i < 128 * 64; i += 64) ws[i] = w1[i];
    int n0 = blockIdx.x * 8;
    for (int i = k; i < 8 * 128; i += 64) ((float*)zs)[i] = z[(size_t)n0 * 128 + i];
    __syncthreads();
    for (int nn = 0; nn < 8; nn++) {
        float u = 0.f;
#pragma unroll 16
        for (int j = 0; j < 128; j++) u += zs[nn][j] * ws[j * 64 + k];
        g_Ut[(size_t)k * NN + n0 + nn] = u;
    }
}

__global__ void __launch_bounds__(64) ep1_kernel(const float* __restrict__ z,
                                                 const float* __restrict__ w1,
                                                 const float* __restrict__ b1,
                                                 const float* __restrict__ w2,
                                                 const float* __restrict__ b2) {
    __shared__ float ws[128 * 64];
    __shared__ float zs[8][128];
    __shared__ float red[8][64];
    int k = threadIdx.x;
    for (int i = k; i < 128 * 64; i += 64) ws[i] = w1[i];
    int n0 = blockIdx.x * 8;
    for (int i = k; i < 8 * 128; i += 64) ((float*)zs)[i] = z[(size_t)n0 * 128 + i];
    __syncthreads();
    float bk = b1[k], wk = w2[k], bo = b2[0];
    for (int nn = 0; nn < 8; nn++) {
        float h = bk;
#pragma unroll 16
        for (int j = 0; j < 128; j++) h += zs[nn][j] * ws[j * 64 + k];
        red[nn][k] = fmaxf(h, 0.f) * wk;
    }
    __syncthreads();
    if (k < 32) {
        for (int nn = 0; nn < 8; nn++) {
            float s = red[nn][k] + red[nn][k + 32];
            for (int off = 16; off; off >>= 1) s += __shfl_down_sync(0xffffffffu, s, off);
            if (k == 0) atomicMax(&g_amax[0], packmax(s + bo, n0 + nn));
        }
    }
}

__global__ void fswap_kernel(FwdPlan p) {
    for (int t = 0; t < TSTEPS; t++) do_swap(p.i1[t], p.i2[t], p.coin[t]);
}

__global__ void c_kernel(const float* __restrict__ z, const float* __restrict__ w1,
                         const float* __restrict__ b1) {
    __shared__ float z0[128], z1[128];
    int k = threadIdx.x;  // 64
    int i1 = unpack_idx(g_amax[0]);
    int e10 = g_ei[i1], e11 = g_ei[EE + i1];
    z0[k] = z[(size_t)e10 * 128 + k];  z0[k + 64] = z[(size_t)e10 * 128 + 64 + k];
    z1[k] = z[(size_t)e11 * 128 + k];  z1[k + 64] = z[(size_t)e11 * 128 + 64 + k];
    __syncthreads();
    float c = b1[k];
#pragma unroll 4
    for (int j = 0; j < 128; j++) {
        c += z0[j] * w1[(size_t)(128 + j) * 64 + k];
        c += z1[j] * w1[(size_t)(256 + j) * 64 + k];
    }
    g_c[k] = c;
    if (k == 0) g_amax[1] = 0ULL;
}

__global__ void scores2_kernel(const float* __restrict__ w2, const float* __restrict__ b2) {
    __shared__ float cs[64], ws[64];
    __shared__ unsigned long long red[256];
    int tid = threadIdx.x;
    int n = blockIdx.x * 256 + tid;
    if (tid < 64) { cs[tid] = g_c[tid]; ws[tid] = w2[tid]; }
    __syncthreads();
    unsigned long long key = 0ULL;
    if (n < NN) {
        float s = b2[0];
#pragma unroll
        for (int k = 0; k < 64; k++) {
            float u = g_Ut[(size_t)k * NN + n] + cs[k];
            s += fmaxf(u, 0.f) * ws[k];
        }
        key = packmax(s, n);
    }
    red[tid] = key;
    __syncthreads();
    for (int off = 128; off; off >>= 1) {
        if (tid < off) { unsigned long long o = red[tid + off]; if (o > red[tid]) red[tid] = o; }
        __syncthreads();
    }
    if (tid == 0) atomicMax(&g_amax[1], red[0]);
}

__global__ void rswap_kernel(int coin) {
    int i1 = unpack_idx(g_amax[0]);
    int i2 = unpack_idx(g_amax[1]);
    do_swap(i1, i2, coin);
}

__global__ void eiout_kernel(float* __restrict__ out) {
    int i = blockIdx.x * blockDim.x + threadIdx.x;
    if (i < 2 * EE) out[(size_t)NN * FF + i] = (float)g_ei[i];
}

// ---------------- host-side JAX threefry (PARTITIONABLE semantics) ----------------
static inline uint32_t rotl32(uint32_t x, int d) { return (x << d) | (x >> (32 - d)); }
static void tf2x32(uint32_t k0, uint32_t k1, uint32_t x0, uint32_t x1,
                   uint32_t& o0, uint32_t& o1) {
    uint32_t ks2 = k0 ^ k1 ^ 0x1BD11BDAu;
    static const int RA[4] = {13, 15, 26, 6}, RB[4] = {17, 29, 16, 24};
    x0 += k0; x1 += k1;
#define RND4(R) for (int i = 0; i < 4; i++) { x0 += x1; x1 = rotl32(x1, R[i]); x1 ^= x0; }
    RND4(RA) x0 += k1;  x1 += ks2 + 1;
    RND4(RB) x0 += ks2; x1 += k0 + 2;
    RND4(RA) x0 += k0;  x1 += k1 + 3;
    RND4(RB) x0 += k1;  x1 += ks2 + 4;
    RND4(RA) x0 += ks2; x1 += k0 + 5;
#undef RND4
    o0 = x0; o1 = x1;
}

struct KP { uint32_t a, b; };
// fold_in(key, t) = threefry(key, (0, t)) -> new key pair (unchanged in partitionable mode)
static KP kfold(KP k, uint32_t t) { KP r; tf2x32(k.a, k.b, 0u, t, r.a, r.b); return r; }
// partitionable split: key_i = threefry(key, (hi=0, lo=i))
static void ksplit(KP k, KP& A, KP& B) {
    tf2x32(k.a, k.b, 0u, 0u, A.a, A.b);
    tf2x32(k.a, k.b, 0u, 1u, B.a, B.b);
}
// partitionable random_bits(32, shape): bits[i] = o0 ^ o1 of threefry(key, (0, i))
static inline uint32_t kbits(KP k, uint32_t i) {
    uint32_t o0, o1; tf2x32(k.a, k.b, 0u, i, o0, o1); return o0 ^ o1;
}
static bool kbern(KP k) { return (kbits(k, 0u) >> 31) == 0; }

// perm = 2-round stable-sort shuffle of arange(EE); return perm[0], perm[1]
static void perm_first2(KP key, int& i1, int& i2) {
    KP kA, s1, kB, s2;
    ksplit(key, kA, s1);   // round 1: key <- kA, subkey s1
    ksplit(kA, kB, s2);    // round 2: subkey s2
    std::vector<uint32_t> b1(EE), b2(EE);
    for (int i = 0; i < EE; i++) b1[i] = kbits(s1, (uint32_t)i);
    for (int i = 0; i < EE; i++) b2[i] = kbits(s2, (uint32_t)i);
    // positions of two smallest (b2[p], p) pairs (stable round-2 sort)
    uint64_t m0 = ~0ULL, m1 = ~0ULL;
    for (int p = 0; p < EE; p++) {
        uint64_t v = ((uint64_t)b2[p] << 32) | (uint32_t)p;
        if (v < m0) { m1 = m0; m0 = v; }
        else if (v < m1) { m1 = v; }
    }
    int p0 = (int)(uint32_t)(m0 & 0xFFFFFFFFu);
    int p1 = (int)(uint32_t)(m1 & 0xFFFFFFFFu);
    // x_after_round1[p] = original index at stable rank p of (b1[j], j)
    std::vector<uint64_t> s(EE);
    for (int j = 0; j < EE; j++) s[j] = ((uint64_t)b1[j] << 32) | (uint32_t)j;
    std::nth_element(s.begin(), s.begin() + p0, s.end());
    i1 = (int)(uint32_t)(s[p0] & 0xFFFFFFFFu);
    std::nth_element(s.begin(), s.begin() + p1, s.end());
    i2 = (int)(uint32_t)(s[p1] & 0xFFFFFFFFu);
}

extern "C" void kernel_launch(void* const* d_in, const int* in_sizes, int n_in,
                              void* d_out, int out_size) {
    int base = n_in - 16;  // 16 trailing weight/bias tensors
    const float* x    = (const float*)d_in[0];
    const int* ei_in  = (const int*)d_in[1];
    const int* dset   = (const int*)d_in[2];
    const float* ew1  = (const float*)d_in[base + 0];
    const float* eb1  = (const float*)d_in[base + 1];
    const float* ew2  = (const float*)d_in[base + 2];
    const float* eb2  = (const float*)d_in[base + 3];
    const float* dw1  = (const float*)d_in[base + 4];
    const float* db1  = (const float*)d_in[base + 5];
    const float* dw2  = (const float*)d_in[base + 6];
    const float* db2  = (const float*)d_in[base + 7];
    const float* p1w1 = (const float*)d_in[base + 8];
    const float* p1b1 = (const float*)d_in[base + 9];
    const float* p1w2 = (const float*)d_in[base + 10];
    const float* p1b2 = (const float*)d_in[base + 11];
    const float* p2w1 = (const float*)d_in[base + 12];
    const float* p2b1 = (const float*)d_in[base + 13];
    const float* p2w2 = (const float*)d_in[base + 14];
    const float* p2b2 = (const float*)d_in[base + 15];
    float* out = (float*)d_out;

    // ---- host plan: forward swap indices/coins + reverse coins (pure constants) ----
    FwdPlan plan;
    int rcoin[TSTEPS];
    for (int t = 0; t < TSTEPS; t++) {
        KP kt = kfold({0u, 1u}, (uint32_t)t);
        KP k1, k2;
        ksplit(kt, k1, k2);
        plan.coin[t] = kbern(k2) ? 1 : 0;
        perm_first2(k1, plan.i1[t], plan.i2[t]);
        rcoin[t] = kbern(kfold({0u, 2u}, (uint32_t)t)) ? 1 : 0;
    }

    int* dev_ei = nullptr; float* lin = nullptr; float* hbuf = nullptr; float* zb = nullptr;
    cudaGetSymbolAddress((void**)&dev_ei, g_ei);
    cudaGetSymbolAddress((void**)&lin, g_lin);
    cudaGetSymbolAddress((void**)&hbuf, g_hbuf);
    cudaGetSymbolAddress((void**)&zb, g_z);

    // ---- original-graph CSR + dinv ----
    copy_ei_kernel<<<(2 * EE + 255) / 256, 256>>>(ei_in);
    zero_cnt_kernel<<<(NN + 255) / 256, 256>>>();
    hist_kernel<<<(EE + 255) / 256, 256>>>(ei_in + EE);
    scan_kernel<<<1, 1024>>>();
    fill_kernel<<<(EE + 255) / 256, 256>>>(ei_in);

    dim3 g2(2, (NN + 127) / 128), g1(1, (NN + 127) / 128);
    // ---- encoder ----
    gemm_kernel<1><<<g2, 256>>>(x, 128, ew1, 256, dset, lin);
    agg_kernel<256, 1><<<(NN * 32 + 255) / 256, 256>>>(lin, eb1, hbuf);
    gemm_kernel<0><<<g1, 256>>>(hbuf, 256, ew2, 128, nullptr, lin);
    agg_kernel<128, 0><<<(NN * 32 + 255) / 256, 256>>>(lin, eb2, zb);

    // ---- edge predictors precompute + forward swaps ----
    ep1_kernel<<<NN / 8, 64>>>(zb, p1w1, p1b1, p1w2, p1b2);
    u_kernel<<<NN / 8, 64>>>(zb, p2w1);
    fswap_kernel<<<1, 1>>>(plan);

    // ---- reverse process ----
    for (int t = 0; t < TSTEPS; t++) {
        c_kernel<<<1, 64>>>(zb, p2w1, p2b1);
        scores2_kernel<<<(NN + 255) / 256, 256>>>(p2w2, p2b2);
        rswap_kernel<<<1, 1>>>(rcoin[t]);
    }

    // ---- final-graph CSR + dinv ----
    zero_cnt_kernel<<<(NN + 255) / 256, 256>>>();
    hist_kernel<<<(EE + 255) / 256, 256>>>(dev_ei + EE);
    scan_kernel<<<1, 1024>>>();
    fill_kernel<<<(EE + 255) / 256, 256>>>(dev_ei);

    // ---- decoder ----
    gemm_kernel<1><<<g2, 256>>>(zb, 128, dw1, 256, dset, lin);
    agg_kernel<256, 1><<<(NN * 32 + 255) / 256, 256>>>(lin, db1, hbuf);
    gemm_kernel<0><<<g1, 256>>>(hbuf, 256, dw2, 128, nullptr, lin);
    agg_kernel<128, 0><<<(NN * 32 + 255) / 256, 256>>>(lin, db2, out);

    // ---- emit final edge index as floats ----
    eiout_kernel<<<(2 * EE + 255) / 256, 256>>>(out);
}

// round 5
// speedup vs baseline: 1.4659x; 1.4659x over previous
#include <cuda_runtime.h>
#include <stdint.h>
#include <vector>
#include <algorithm>

#define NN 50000
#define EE 800000
#define FF 128
#define TSTEPS 5
#define SCAN_NB 128

// ---------------- static device buffers ----------------
__device__ int   g_ei[2 * EE];
__device__ int   g_cnt[NN];
__device__ int   g_rowptr[NN + 1];
__device__ int   g_cursor[NN];
__device__ int   g_csr[EE];
__device__ int   g_bsum[SCAN_NB];
__device__ float g_dinv[NN];
__device__ float g_lin[(size_t)NN * 256];
__device__ float g_hbuf[(size_t)NN * 256];
__device__ float g_z[(size_t)NN * 128];
__device__ float g_Ut[(size_t)64 * NN];
__device__ unsigned long long g_amax[2];

struct FwdPlan { int i1[TSTEPS]; int i2[TSTEPS]; int coin[TSTEPS]; };

__device__ __forceinline__ float tf32rna(float x) {
    uint32_t u; asm("cvt.rna.tf32.f32 %0, %1;" : "=r"(u) : "f"(x));
    return __uint_as_float(u);
}
__device__ __forceinline__ unsigned long long packmax(float v, int idx) {
    unsigned u = __float_as_uint(v);
    u ^= ((unsigned)((int)u >> 31)) | 0x80000000u;
    return ((unsigned long long)u << 32) | (unsigned)(0xFFFFFFFFu - (unsigned)idx);
}
__device__ __forceinline__ int unpack_idx(unsigned long long k) {
    return (int)(0xFFFFFFFFu - (unsigned)(k & 0xFFFFFFFFu));
}
__device__ __forceinline__ void do_swap(int i1, int i2, int coin) {
    int a = g_ei[i1], b = g_ei[EE + i1];
    int c = g_ei[i2], d = g_ei[EE + i2];
    int n10, n11, n20, n21;
    if (coin) { n10 = a; n11 = d; n20 = c; n21 = b; }
    else      { n10 = a; n11 = c; n20 = b; n21 = d; }
    g_ei[i1] = n10; g_ei[EE + i1] = n11;
    g_ei[i2] = n20; g_ei[EE + i2] = n21;
}

// ---------------- graph structure ----------------
__global__ void copy_ei_kernel(const int* __restrict__ ei) {
    int i = blockIdx.x * blockDim.x + threadIdx.x;
    if (i < 2 * EE) g_ei[i] = ei[i];
    if (i == 0) { g_amax[0] = 0ULL; g_amax[1] = 0ULL; }
}
__global__ void zero_cnt_kernel() {
    int i = blockIdx.x * blockDim.x + threadIdx.x;
    if (i < NN) g_cnt[i] = 0;
}
__global__ void hist_kernel(const int* __restrict__ dst) {
    int e = blockIdx.x * blockDim.x + threadIdx.x;
    if (e < EE) atomicAdd(&g_cnt[dst[e]], 1);
}

// 3-phase scan: block partial sums -> scan of partials -> fixup write
__global__ void scanA_kernel() {
    const int CH = (NN + SCAN_NB - 1) / SCAN_NB;   // 391
    const int TC = (CH + 255) / 256;               // 2
    int b = blockIdx.x, t = threadIdx.x;
    int beg = b * CH;
    int s = 0;
#pragma unroll
    for (int i = 0; i < TC; i++) {
        int n = beg + t * TC + i;
        if (n < beg + CH && n < NN) s += g_cnt[n];
    }
    __shared__ int sm[8];
    for (int o = 16; o; o >>= 1) s += __shfl_down_sync(~0u, s, o);
    if ((t & 31) == 0) sm[t >> 5] = s;
    __syncthreads();
    if (t < 8) {
        int v = sm[t];
        for (int o = 4; o; o >>= 1) v += __shfl_down_sync(0xffu, v, o);
        if (t == 0) g_bsum[b] = v;
    }
}
__global__ void scanB_kernel() {   // SCAN_NB=128 threads
    int t = threadIdx.x;
    int v = g_bsum[t];
    int x = v;
    for (int o = 1; o < 32; o <<= 1) {
        int y = __shfl_up_sync(~0u, x, o);
        if ((t & 31) >= o) x += y;
    }
    __shared__ int ws[4];
    if ((t & 31) == 31) ws[t >> 5] = x;
    __syncthreads();
    int add = 0;
#pragma unroll
    for (int wI = 0; wI < 4; wI++) if (wI < (t >> 5)) add += ws[wI];
    g_bsum[t] = x + add - v;   // exclusive
}
__global__ void scanC_kernel() {
    const int CH = (NN + SCAN_NB - 1) / SCAN_NB;
    const int TC = (CH + 255) / 256;
    int b = blockIdx.x, t = threadIdx.x;
    int beg = b * CH;
    int c[TC]; int s = 0;
#pragma unroll
    for (int i = 0; i < TC; i++) {
        int n = beg + t * TC + i;
        c[i] = (n < beg + CH && n < NN) ? g_cnt[n] : 0;
        s += c[i];
    }
    int x = s;
    for (int o = 1; o < 32; o <<= 1) {
        int y = __shfl_up_sync(~0u, x, o);
        if ((t & 31) >= o) x += y;
    }
    __shared__ int ws[8];
    if ((t & 31) == 31) ws[t >> 5] = x;
    __syncthreads();
    int add = 0;
#pragma unroll
    for (int wI = 0; wI < 8; wI++) if (wI < (t >> 5)) add += ws[wI];
    int run = g_bsum[b] + x + add - s;   // global exclusive prefix at this thread
#pragma unroll
    for (int i = 0; i < TC; i++) {
        int n = beg + t * TC + i;
        if (n < beg + CH && n < NN) {
            g_rowptr[n] = run; g_cursor[n] = run;
            float df = (float)(c[i] + 1);
            float r = rsqrtf(df);
            r = r * (1.5f - 0.5f * df * r * r);
            g_dinv[n] = r;
            run += c[i];
        }
    }
    if (b == 0 && t == 0) g_rowptr[NN] = EE;
}
__global__ void fill_kernel(const int* __restrict__ ei) {
    int e = blockIdx.x * blockDim.x + threadIdx.x;
    if (e < EE) {
        int s = ei[e], d = ei[EE + e];
        int pos = atomicAdd(&g_cursor[d], 1);
        g_csr[pos] = s;
    }
}

// ---------------- tensor-core GEMM (3xTF32, fp32-accurate) ----------------
// out[m][c] = dinv[m]*(A[m]@W + Wd[K+deg[m]])
__device__ __forceinline__ void mma8(float d[4], const uint32_t a[4], const uint32_t b[2]) {
    asm("mma.sync.aligned.m16n8k8.row.col.f32.tf32.tf32.f32 "
        "{%0,%1,%2,%3}, {%4,%5,%6,%7}, {%8,%9}, {%0,%1,%2,%3};"
        : "+f"(d[0]), "+f"(d[1]), "+f"(d[2]), "+f"(d[3])
        : "r"(a[0]), "r"(a[1]), "r"(a[2]), "r"(a[3]), "r"(b[0]), "r"(b[1]));
}

template <int ONEHOT>
__global__ void __launch_bounds__(256) mma_gemm_kernel(
    const float* __restrict__ A, int K, const float* __restrict__ W, int C,
    const int* __restrict__ deg, float* __restrict__ out) {
    const int SA = 20;    // stride%32==4 -> conflict-free A fragments
    const int SB = 136;   // stride%32==8 -> conflict-free B fragments
    __shared__ float Ahi[128 * SA], Alo[128 * SA];
    __shared__ float Bhi[16 * SB],  Blo[16 * SB];
    int bm = blockIdx.y * 128, bn = blockIdx.x * 128;
    int tid = threadIdx.x, lane = tid & 31, w = tid >> 5;
    int wm = w >> 1, wn = w & 1;   // 4x2 warp grid, warp tile 32x64

    float acc[2][8][4];
#pragma unroll
    for (int mt = 0; mt < 2; mt++)
#pragma unroll
        for (int nt = 0; nt < 8; nt++)
#pragma unroll
            for (int r = 0; r < 4; r++) acc[mt][nt][r] = 0.f;

    for (int kt = 0; kt < K; kt += 16) {
        // A tile 128x16 -> hi/lo
#pragma unroll
        for (int it = 0; it < 2; it++) {
            int f = tid + it * 256;
            int m = f >> 2, k4 = (f & 3) << 2;
            float4 v = make_float4(0.f, 0.f, 0.f, 0.f);
            if (bm + m < NN) v = *(const float4*)&A[(size_t)(bm + m) * K + kt + k4];
            float hx = tf32rna(v.x), hy = tf32rna(v.y), hz = tf32rna(v.z), hw = tf32rna(v.w);
            int o = m * SA + k4;
            Ahi[o] = hx; Ahi[o + 1] = hy; Ahi[o + 2] = hz; Ahi[o + 3] = hw;
            Alo[o]     = tf32rna(v.x - hx); Alo[o + 1] = tf32rna(v.y - hy);
            Alo[o + 2] = tf32rna(v.z - hz); Alo[o + 3] = tf32rna(v.w - hw);
        }
        // B tile 16x128 -> hi/lo
#pragma unroll
        for (int it = 0; it < 2; it++) {
            int f = tid + it * 256;
            int k = f >> 5, n4 = (f & 31) << 2;
            float4 v = *(const float4*)&W[(size_t)(kt + k) * C + bn + n4];
            float hx = tf32rna(v.x), hy = tf32rna(v.y), hz = tf32rna(v.z), hw = tf32rna(v.w);
            int o = k * SB + n4;
            Bhi[o] = hx; Bhi[o + 1] = hy; Bhi[o + 2] = hz; Bhi[o + 3] = hw;
            Blo[o]     = tf32rna(v.x - hx); Blo[o + 1] = tf32rna(v.y - hy);
            Blo[o + 2] = tf32rna(v.z - hz); Blo[o + 3] = tf32rna(v.w - hw);
        }
        __syncthreads();
#pragma unroll
        for (int kk = 0; kk < 16; kk += 8) {
            uint32_t ah[2][4], al[2][4];
#pragma unroll
            for (int mt = 0; mt < 2; mt++) {
                int mr = wm * 32 + mt * 16 + (lane >> 2);
                int kc = kk + (lane & 3);
                ah[mt][0] = __float_as_uint(Ahi[mr * SA + kc]);
                ah[mt][1] = __float_as_uint(Ahi[(mr + 8) * SA + kc]);
                ah[mt][2] = __float_as_uint(Ahi[mr * SA + kc + 4]);
                ah[mt][3] = __float_as_uint(Ahi[(mr + 8) * SA + kc + 4]);
                al[mt][0] = __float_as_uint(Alo[mr * SA + kc]);
                al[mt][1] = __float_as_uint(Alo[(mr + 8) * SA + kc]);
                al[mt][2] = __float_as_uint(Alo[mr * SA + kc + 4]);
                al[mt][3] = __float_as_uint(Alo[(mr + 8) * SA + kc + 4]);
            }
#pragma unroll
            for (int nt = 0; nt < 8; nt++) {
                int nc = wn * 64 + nt * 8 + (lane >> 2);
                int kr = kk + (lane & 3);
                uint32_t bh[2] = { __float_as_uint(Bhi[kr * SB + nc]),
                                   __float_as_uint(Bhi[(kr + 4) * SB + nc]) };
                uint32_t bl[2] = { __float_as_uint(Blo[kr * SB + nc]),
                                   __float_as_uint(Blo[(kr + 4) * SB + nc]) };
#pragma unroll
                for (int mt = 0; mt < 2; mt++) {
                    mma8(acc[mt][nt], ah[mt], bh);
                    mma8(acc[mt][nt], ah[mt], bl);
                    mma8(acc[mt][nt], al[mt], bh);
                }
            }
        }
        __syncthreads();
    }
    // epilogue: +onehot row, *dinv
#pragma unroll
    for (int mt = 0; mt < 2; mt++)
#pragma unroll
        for (int rr = 0; rr < 2; rr++) {
            int row = bm + wm * 32 + mt * 16 + (lane >> 2) + rr * 8;
            if (row < NN) {
                float dv = g_dinv[row];
                const float* wd = nullptr;
                if (ONEHOT) wd = W + (size_t)(K + deg[row]) * C + bn;
#pragma unroll
                for (int nt = 0; nt < 8; nt++) {
                    int col = wn * 64 + nt * 8 + (lane & 3) * 2;
                    float v0 = acc[mt][nt][rr * 2 + 0];
                    float v1 = acc[mt][nt][rr * 2 + 1];
                    if (ONEHOT) { v0 += wd[col]; v1 += wd[col + 1]; }
                    *(float2*)&out[(size_t)row * C + bn + col] = make_float2(v0 * dv, v1 * dv);
                }
            }
        }
}

// ---------------- aggregation: out[n] = dinv[n]*(g[n] + sum_csr g[src]) + b ----------------
template <int C, int RELU>
__global__ void agg_kernel(const float* __restrict__ g, const float* __restrict__ bias,
                           float* __restrict__ out) {
    int warp = (blockIdx.x * blockDim.x + threadIdx.x) >> 5;
    int lane = threadIdx.x & 31;
    if (warp >= NN) return;
    int n = warp;
    const int V = C / 4;
    const float4* g4 = (const float4*)g;
    float4 a0 = g4[(size_t)n * V + lane];
    float4 a1 = make_float4(0.f, 0.f, 0.f, 0.f);
    if (C == 256) a1 = g4[(size_t)n * V + 32 + lane];
    int beg = g_rowptr[n], end = g_rowptr[n + 1];
    for (int p = beg; p < end; ++p) {
        int s = g_csr[p];
        float4 b0 = g4[(size_t)s * V + lane];
        a0.x += b0.x; a0.y += b0.y; a0.z += b0.z; a0.w += b0.w;
        if (C == 256) {
            float4 b1v = g4[(size_t)s * V + 32 + lane];
            a1.x += b1v.x; a1.y += b1v.y; a1.z += b1v.z; a1.w += b1v.w;
        }
    }
    float dv = g_dinv[n];
    const float4* bias4 = (const float4*)bias;
    float4 bb = bias4[lane];
    a0.x = a0.x * dv + bb.x; a0.y = a0.y * dv + bb.y;
    a0.z = a0.z * dv + bb.z; a0.w = a0.w * dv + bb.w;
    if (RELU) {
        a0.x = fmaxf(a0.x, 0.f); a0.y = fmaxf(a0.y, 0.f);
        a0.z = fmaxf(a0.z, 0.f); a0.w = fmaxf(a0.w, 0.f);
    }
    ((float4*)out)[(size_t)n * V + lane] = a0;
    if (C == 256) {
        float4 b2 = bias4[32 + lane];
        a1.x = a1.x * dv + b2.x; a1.y = a1.y * dv + b2.y;
        a1.z = a1.z * dv + b2.z; a1.w = a1.w * dv + b2.w;
        if (RELU) {
            a1.x = fmaxf(a1.x, 0.f); a1.y = fmaxf(a1.y, 0.f);
            a1.z = fmaxf(a1.z, 0.f); a1.w = fmaxf(a1.w, 0.f);
        }
        ((float4*)out)[(size_t)n * V + 32 + lane] = a1;
    }
}

// ---------------- edge predictors ----------------
__global__ void __launch_bounds__(64) u_kernel(const float* __restrict__ z,
                                               const float* __restrict__ w1) {
    __shared__ float ws[128 * 64];
    __shared__ float zs[8][128];
    int k = threadIdx.x;
    for (int i = k; i < 128 * 64; i += 64) ws[i] = w1[i];
    int n0 = blockIdx.x * 8;
    for (int i = k; i < 8 * 128; i += 64) ((float*)zs)[i] = z[(size_t)n0 * 128 + i];
    __syncthreads();
    for (int nn = 0; nn < 8; nn++) {
        float u = 0.f;
#pragma unroll 16
        for (int j = 0; j < 128; j++) u += zs[nn][j] * ws[j * 64 + k];
        g_Ut[(size_t)k * NN + n0 + nn] = u;
    }
}

__global__ void __launch_bounds__(64) ep1_kernel(const float* __restrict__ z,
                                                 const float* __restrict__ w1,
                                                 const float* __restrict__ b1,
                                                 const float* __restrict__ w2,
                                                 const float* __restrict__ b2) {
    __shared__ float ws[128 * 64];
    __shared__ float zs[8][128];
    __shared__ float red[8][64];
    int k = threadIdx.x;
    for (int i = k; i < 128 * 64; i += 64) ws[i] = w1[i];
    int n0 = blockIdx.x * 8;
    for (int i = k; i < 8 * 128; i += 64) ((float*)zs)[i] = z[(size_t)n0 * 128 + i];
    __syncthreads();
    float bk = b1[k], wk = w2[k], bo = b2[0];
    for (int nn = 0; nn < 8; nn++) {
        float h = bk;
#pragma unroll 16
        for (int j = 0; j < 128; j++) h += zs[nn][j] * ws[j * 64 + k];
        red[nn][k] = fmaxf(h, 0.f) * wk;
    }
    __syncthreads();
    if (k < 32) {
        for (int nn = 0; nn < 8; nn++) {
            float s = red[nn][k] + red[nn][k + 32];
            for (int off = 16; off; off >>= 1) s += __shfl_down_sync(0xffffffffu, s, off);
            if (k == 0) atomicMax(&g_amax[0], packmax(s + bo, n0 + nn));
        }
    }
}

__global__ void fswap_kernel(FwdPlan p) {
    for (int t = 0; t < TSTEPS; t++) do_swap(p.i1[t], p.i2[t], p.coin[t]);
}

// scores2 with fused c-computation (each block computes c redundantly)
__global__ void scores2_kernel(const float* __restrict__ z, const float* __restrict__ w1,
                               const float* __restrict__ b1, const float* __restrict__ w2,
                               const float* __restrict__ b2) {
    __shared__ float z01[256];
    __shared__ float cs[64], ws[64];
    __shared__ unsigned long long red[256];
    int tid = threadIdx.x;
    int i1 = unpack_idx(g_amax[0]);
    int e10 = g_ei[i1], e11 = g_ei[EE + i1];
    if (tid < 128) z01[tid] = z[(size_t)e10 * 128 + tid];
    else           z01[tid] = z[(size_t)e11 * 128 + (tid - 128)];
    __syncthreads();
    if (tid < 64) {
        float c = b1[tid];
#pragma unroll 8
        for (int j = 0; j < 256; j++) c += z01[j] * w1[(size_t)(128 + j) * 64 + tid];
        cs[tid] = c; ws[tid] = w2[tid];
    }
    __syncthreads();
    int n = blockIdx.x * 256 + tid;
    unsigned long long key = 0ULL;
    if (n < NN) {
        float s = b2[0];
#pragma unroll
        for (int k = 0; k < 64; k++) {
            float u = g_Ut[(size_t)k * NN + n] + cs[k];
            s += fmaxf(u, 0.f) * ws[k];
        }
        key = packmax(s, n);
    }
    red[tid] = key;
    __syncthreads();
    for (int off = 128; off; off >>= 1) {
        if (tid < off) { unsigned long long o = red[tid + off]; if (o > red[tid]) red[tid] = o; }
        __syncthreads();
    }
    if (tid == 0) atomicMax(&g_amax[1], red[0]);
}

__global__ void rswap_kernel(int coin) {
    int i1 = unpack_idx(g_amax[0]);
    int i2 = unpack_idx(g_amax[1]);
    do_swap(i1, i2, coin);
    g_amax[1] = 0ULL;   // ready for next step
}

__global__ void eiout_kernel(float* __restrict__ out) {
    int i = blockIdx.x * blockDim.x + threadIdx.x;
    if (i < 2 * EE) out[(size_t)NN * FF + i] = (float)g_ei[i];
}

// ---------------- host-side JAX threefry (partitionable semantics) ----------------
static inline uint32_t rotl32(uint32_t x, int d) { return (x << d) | (x >> (32 - d)); }
static void tf2x32(uint32_t k0, uint32_t k1, uint32_t x0, uint32_t x1,
                   uint32_t& o0, uint32_t& o1) {
    uint32_t ks2 = k0 ^ k1 ^ 0x1BD11BDAu;
    static const int RA[4] = {13, 15, 26, 6}, RB[4] = {17, 29, 16, 24};
    x0 += k0; x1 += k1;
#define RND4(R) for (int i = 0; i < 4; i++) { x0 += x1; x1 = rotl32(x1, R[i]); x1 ^= x0; }
    RND4(RA) x0 += k1;  x1 += ks2 + 1;
    RND4(RB) x0 += ks2; x1 += k0 + 2;
    RND4(RA) x0 += k0;  x1 += k1 + 3;
    RND4(RB) x0 += k1;  x1 += ks2 + 4;
    RND4(RA) x0 += ks2; x1 += k0 + 5;
#undef RND4
    o0 = x0; o1 = x1;
}

struct KP { uint32_t a, b; };
static KP kfold(KP k, uint32_t t) { KP r; tf2x32(k.a, k.b, 0u, t, r.a, r.b); return r; }
static void ksplit(KP k, KP& A, KP& B) {
    tf2x32(k.a, k.b, 0u, 0u, A.a, A.b);
    tf2x32(k.a, k.b, 0u, 1u, B.a, B.b);
}
static inline uint32_t kbits(KP k, uint32_t i) {
    uint32_t o0, o1; tf2x32(k.a, k.b, 0u, i, o0, o1); return o0 ^ o1;
}
static bool kbern(KP k) { return (kbits(k, 0u) >> 31) == 0; }

static void perm_first2(KP key, int& i1, int& i2) {
    KP kA, s1, kB, s2;
    ksplit(key, kA, s1);
    ksplit(kA, kB, s2);
    std::vector<uint32_t> b1(EE), b2(EE);
    for (int i = 0; i < EE; i++) b1[i] = kbits(s1, (uint32_t)i);
    for (int i = 0; i < EE; i++) b2[i] = kbits(s2, (uint32_t)i);
    uint64_t m0 = ~0ULL, m1 = ~0ULL;
    for (int p = 0; p < EE; p++) {
        uint64_t v = ((uint64_t)b2[p] << 32) | (uint32_t)p;
        if (v < m0) { m1 = m0; m0 = v; }
        else if (v < m1) { m1 = v; }
    }
    int p0 = (int)(uint32_t)(m0 & 0xFFFFFFFFu);
    int p1 = (int)(uint32_t)(m1 & 0xFFFFFFFFu);
    std::vector<uint64_t> s(EE);
    for (int j = 0; j < EE; j++) s[j] = ((uint64_t)b1[j] << 32) | (uint32_t)j;
    std::nth_element(s.begin(), s.begin() + p0, s.end());
    i1 = (int)(uint32_t)(s[p0] & 0xFFFFFFFFu);
    std::nth_element(s.begin(), s.begin() + p1, s.end());
    i2 = (int)(uint32_t)(s[p1] & 0xFFFFFFFFu);
}

extern "C" void kernel_launch(void* const* d_in, const int* in_sizes, int n_in,
                              void* d_out, int out_size) {
    int base = n_in - 16;
    const float* x    = (const float*)d_in[0];
    const int* ei_in  = (const int*)d_in[1];
    const int* dset   = (const int*)d_in[2];
    const float* ew1  = (const float*)d_in[base + 0];
    const float* eb1  = (const float*)d_in[base + 1];
    const float* ew2  = (const float*)d_in[base + 2];
    const float* eb2  = (const float*)d_in[base + 3];
    const float* dw1  = (const float*)d_in[base + 4];
    const float* db1  = (const float*)d_in[base + 5];
    const float* dw2  = (const float*)d_in[base + 6];
    const float* db2  = (const float*)d_in[base + 7];
    const float* p1w1 = (const float*)d_in[base + 8];
    const float* p1b1 = (const float*)d_in[base + 9];
    const float* p1w2 = (const float*)d_in[base + 10];
    const float* p1b2 = (const float*)d_in[base + 11];
    const float* p2w1 = (const float*)d_in[base + 12];
    const float* p2b1 = (const float*)d_in[base + 13];
    const float* p2w2 = (const float*)d_in[base + 14];
    const float* p2b2 = (const float*)d_in[base + 15];
    float* out = (float*)d_out;

    // ---- host plan (pure PRNG constants, untimed) ----
    FwdPlan plan;
    int rcoin[TSTEPS];
    for (int t = 0; t < TSTEPS; t++) {
        KP kt = kfold({0u, 1u}, (uint32_t)t);
        KP k1, k2;
        ksplit(kt, k1, k2);
        plan.coin[t] = kbern(k2) ? 1 : 0;
        perm_first2(k1, plan.i1[t], plan.i2[t]);
        rcoin[t] = kbern(kfold({0u, 2u}, (uint32_t)t)) ? 1 : 0;
    }

    int* dev_ei = nullptr; float* lin = nullptr; float* hbuf = nullptr; float* zb = nullptr;
    cudaGetSymbolAddress((void**)&dev_ei, g_ei);
    cudaGetSymbolAddress((void**)&lin, g_lin);
    cudaGetSymbolAddress((void**)&hbuf, g_hbuf);
    cudaGetSymbolAddress((void**)&zb, g_z);

    // ---- original-graph CSR + dinv ----
    copy_ei_kernel<<<(2 * EE + 255) / 256, 256>>>(ei_in);
    zero_cnt_kernel<<<(NN + 255) / 256, 256>>>();
    hist_kernel<<<(EE + 255) / 256, 256>>>(ei_in + EE);
    scanA_kernel<<<SCAN_NB, 256>>>();
    scanB_kernel<<<1, SCAN_NB>>>();
    scanC_kernel<<<SCAN_NB, 256>>>();
    fill_kernel<<<(EE + 255) / 256, 256>>>(ei_in);

    dim3 g2(2, (NN + 127) / 128), g1(1, (NN + 127) / 128);
    // ---- encoder ----
    mma_gemm_kernel<1><<<g2, 256>>>(x, 128, ew1, 256, dset, lin);
    agg_kernel<256, 1><<<(NN * 32 + 255) / 256, 256>>>(lin, eb1, hbuf);
    mma_gemm_kernel<0><<<g1, 256>>>(hbuf, 256, ew2, 128, nullptr, lin);
    agg_kernel<128, 0><<<(NN * 32 + 255) / 256, 256>>>(lin, eb2, zb);

    // ---- edge predictors precompute + forward swaps ----
    ep1_kernel<<<NN / 8, 64>>>(zb, p1w1, p1b1, p1w2, p1b2);
    u_kernel<<<NN / 8, 64>>>(zb, p2w1);
    fswap_kernel<<<1, 1>>>(plan);

    // ---- reverse process ----
    for (int t = 0; t < TSTEPS; t++) {
        scores2_kernel<<<(NN + 255) / 256, 256>>>(zb, p2w1, p2b1, p2w2, p2b2);
        rswap_kernel<<<1, 1>>>(rcoin[t]);
    }

    // ---- final-graph CSR + dinv ----
    zero_cnt_kernel<<<(NN + 255) / 256, 256>>>();
    hist_kernel<<<(EE + 255) / 256, 256>>>(dev_ei + EE);
    scanA_kernel<<<SCAN_NB, 256>>>();
    scanB_kernel<<<1, SCAN_NB>>>();
    scanC_kernel<<<SCAN_NB, 256>>>();
    fill_kernel<<<(EE + 255) / 256, 256>>>(dev_ei);

    // ---- decoder ----
    mma_gemm_kernel<1><<<g2, 256>>>(zb, 128, dw1, 256, dset, lin);
    agg_kernel<256, 1><<<(NN * 32 + 255) / 256, 256>>>(lin, db1, hbuf);
    mma_gemm_kernel<0><<<g1, 256>>>(hbuf, 256, dw2, 128, nullptr, lin);
    agg_kernel<128, 0><<<(NN * 32 + 255) / 256, 256>>>(lin, db2, out);

    // ---- emit final edge index as floats ----
    eiout_kernel<<<(2 * EE + 255) / 256, 256>>>(out);
}

// round 6
// speedup vs baseline: 1.8834x; 1.2848x over previous
#include <cuda_runtime.h>
#include <stdint.h>
#include <vector>
#include <algorithm>

#define NN 50000
#define EE 800000
#define FF 128
#define TSTEPS 5
#define SCAN_NB 128

// ---------------- static device buffers ----------------
__device__ int   g_ei[2 * EE];
__device__ int   g_cnt[NN];
__device__ int   g_rowptr[NN + 1];
__device__ int   g_cursor[NN];
__device__ int   g_csr[EE];
__device__ int   g_bsum[SCAN_NB];
__device__ int   g_done;
__device__ float g_dinv[NN];
__device__ float g_lin[(size_t)NN * 256];
__device__ float g_hbuf[(size_t)NN * 256];
__device__ float g_z[(size_t)NN * 128];
__device__ float g_Ut[(size_t)64 * NN];
__device__ float g_Whi[4 * 32768];
__device__ float g_Wlo[2 * 32768];
__device__ unsigned long long g_amax[2];

struct FwdPlan { int i1[TSTEPS]; int i2[TSTEPS]; int coin[TSTEPS]; };

__device__ __forceinline__ float tf32rna(float x) {
    uint32_t u; asm("cvt.rna.tf32.f32 %0, %1;" : "=r"(u) : "f"(x));
    return __uint_as_float(u);
}
__device__ __forceinline__ unsigned long long packmax(float v, int idx) {
    unsigned u = __float_as_uint(v);
    u ^= ((unsigned)((int)u >> 31)) | 0x80000000u;
    return ((unsigned long long)u << 32) | (unsigned)(0xFFFFFFFFu - (unsigned)idx);
}
__device__ __forceinline__ int unpack_idx(unsigned long long k) {
    return (int)(0xFFFFFFFFu - (unsigned)(k & 0xFFFFFFFFu));
}
__device__ __forceinline__ void do_swap(int i1, int i2, int coin) {
    int a = g_ei[i1], b = g_ei[EE + i1];
    int c = g_ei[i2], d = g_ei[EE + i2];
    int n10, n11, n20, n21;
    if (coin) { n10 = a; n11 = d; n20 = c; n21 = b; }
    else      { n10 = a; n11 = c; n20 = b; n21 = d; }
    g_ei[i1] = n10; g_ei[EE + i1] = n11;
    g_ei[i2] = n20; g_ei[EE + i2] = n21;
}

// ---------------- W split precompute ----------------
__global__ void wsplit_kernel(const float* __restrict__ W, int len,
                              float* __restrict__ hi, float* __restrict__ lo) {
    int i = blockIdx.x * blockDim.x + threadIdx.x;
    if (i < len) {
        float v = W[i];
        float h = tf32rna(v);
        hi[i] = h;
        lo[i] = tf32rna(v - h);
    }
}
__global__ void wround_kernel(const float* __restrict__ W, int len, float* __restrict__ hi) {
    int i = blockIdx.x * blockDim.x + threadIdx.x;
    if (i < len) hi[i] = tf32rna(W[i]);
}

// ---------------- graph structure ----------------
__global__ void copy_ei_kernel(const int* __restrict__ ei) {
    int i = blockIdx.x * blockDim.x + threadIdx.x;
    if (i < 2 * EE) g_ei[i] = ei[i];
    if (i < NN) g_cnt[i] = 0;
    if (i == 0) { g_amax[0] = 0ULL; g_amax[1] = 0ULL; g_done = 0; }
}
__global__ void zero_cnt_kernel() {
    int i = blockIdx.x * blockDim.x + threadIdx.x;
    if (i < NN) g_cnt[i] = 0;
}
__global__ void hist_kernel(const int* __restrict__ dst) {
    int e = blockIdx.x * blockDim.x + threadIdx.x;
    if (e < EE) atomicAdd(&g_cnt[dst[e]], 1);
}
__global__ void scanA_kernel() {
    const int CH = (NN + SCAN_NB - 1) / SCAN_NB;
    const int TC = (CH + 255) / 256;
    int b = blockIdx.x, t = threadIdx.x;
    int beg = b * CH;
    int s = 0;
#pragma unroll
    for (int i = 0; i < TC; i++) {
        int n = beg + t * TC + i;
        if (n < beg + CH && n < NN) s += g_cnt[n];
    }
    __shared__ int sm[8];
    for (int o = 16; o; o >>= 1) s += __shfl_down_sync(~0u, s, o);
    if ((t & 31) == 0) sm[t >> 5] = s;
    __syncthreads();
    if (t < 8) {
        int v = sm[t];
        for (int o = 4; o; o >>= 1) v += __shfl_down_sync(0xffu, v, o);
        if (t == 0) g_bsum[b] = v;
    }
}
__global__ void scanB_kernel() {
    int t = threadIdx.x;
    int v = g_bsum[t];
    int x = v;
    for (int o = 1; o < 32; o <<= 1) {
        int y = __shfl_up_sync(~0u, x, o);
        if ((t & 31) >= o) x += y;
    }
    __shared__ int ws[4];
    if ((t & 31) == 31) ws[t >> 5] = x;
    __syncthreads();
    int add = 0;
#pragma unroll
    for (int wI = 0; wI < 4; wI++) if (wI < (t >> 5)) add += ws[wI];
    g_bsum[t] = x + add - v;
}
__global__ void scanC_kernel() {
    const int CH = (NN + SCAN_NB - 1) / SCAN_NB;
    const int TC = (CH + 255) / 256;
    int b = blockIdx.x, t = threadIdx.x;
    int beg = b * CH;
    int c[TC]; int s = 0;
#pragma unroll
    for (int i = 0; i < TC; i++) {
        int n = beg + t * TC + i;
        c[i] = (n < beg + CH && n < NN) ? g_cnt[n] : 0;
        s += c[i];
    }
    int x = s;
    for (int o = 1; o < 32; o <<= 1) {
        int y = __shfl_up_sync(~0u, x, o);
        if ((t & 31) >= o) x += y;
    }
    __shared__ int ws[8];
    if ((t & 31) == 31) ws[t >> 5] = x;
    __syncthreads();
    int add = 0;
#pragma unroll
    for (int wI = 0; wI < 8; wI++) if (wI < (t >> 5)) add += ws[wI];
    int run = g_bsum[b] + x + add - s;
#pragma unroll
    for (int i = 0; i < TC; i++) {
        int n = beg + t * TC + i;
        if (n < beg + CH && n < NN) {
            g_rowptr[n] = run; g_cursor[n] = run;
            float df = (float)(c[i] + 1);
            float r = rsqrtf(df);
            r = r * (1.5f - 0.5f * df * r * r);
            g_dinv[n] = r;
            run += c[i];
        }
    }
    if (b == 0 && t == 0) g_rowptr[NN] = EE;
}
__global__ void fill_kernel(const int* __restrict__ ei) {
    int e = blockIdx.x * blockDim.x + threadIdx.x;
    if (e < EE) {
        int s = ei[e], d = ei[EE + e];
        int pos = atomicAdd(&g_cursor[d], 1);
        g_csr[pos] = s;
    }
}

// ---------------- tensor-core GEMM ----------------
// NSPLIT==3: 3xTF32 (fp32-accurate); NSPLIT==1: plain tf32
__device__ __forceinline__ void mma8(float d[4], const uint32_t a[4], const uint32_t b[2]) {
    asm("mma.sync.aligned.m16n8k8.row.col.f32.tf32.tf32.f32 "
        "{%0,%1,%2,%3}, {%4,%5,%6,%7}, {%8,%9}, {%0,%1,%2,%3};"
        : "+f"(d[0]), "+f"(d[1]), "+f"(d[2]), "+f"(d[3])
        : "r"(a[0]), "r"(a[1]), "r"(a[2]), "r"(a[3]), "r"(b[0]), "r"(b[1]));
}

template <int ONEHOT, int NSPLIT>
__global__ void __launch_bounds__(256) mma_gemm_kernel(
    const float* __restrict__ A, int K,
    const float* __restrict__ Whi, const float* __restrict__ Wlo,
    const float* __restrict__ Wraw, int C,
    const int* __restrict__ deg, float* __restrict__ out) {
    const int SA = 20;
    const int SB = 136;
    __shared__ float Ahi[128 * SA];
    __shared__ float Alo[(NSPLIT == 3) ? 128 * SA : 1];
    __shared__ float Bhi[16 * SB];
    __shared__ float Blo[(NSPLIT == 3) ? 16 * SB : 1];
    int bm = blockIdx.y * 128, bn = blockIdx.x * 128;
    int tid = threadIdx.x, lane = tid & 31, w = tid >> 5;
    int wm = w >> 1, wn = w & 1;

    float acc[2][8][4];
#pragma unroll
    for (int mt = 0; mt < 2; mt++)
#pragma unroll
        for (int nt = 0; nt < 8; nt++)
#pragma unroll
            for (int r = 0; r < 4; r++) acc[mt][nt][r] = 0.f;

    for (int kt = 0; kt < K; kt += 16) {
#pragma unroll
        for (int it = 0; it < 2; it++) {
            int f = tid + it * 256;
            int m = f >> 2, k4 = (f & 3) << 2;
            float4 v = make_float4(0.f, 0.f, 0.f, 0.f);
            if (bm + m < NN) v = *(const float4*)&A[(size_t)(bm + m) * K + kt + k4];
            float hx = tf32rna(v.x), hy = tf32rna(v.y), hz = tf32rna(v.z), hw = tf32rna(v.w);
            int o = m * SA + k4;
            Ahi[o] = hx; Ahi[o + 1] = hy; Ahi[o + 2] = hz; Ahi[o + 3] = hw;
            if (NSPLIT == 3) {
                Alo[o]     = tf32rna(v.x - hx); Alo[o + 1] = tf32rna(v.y - hy);
                Alo[o + 2] = tf32rna(v.z - hz); Alo[o + 3] = tf32rna(v.w - hw);
            }
        }
#pragma unroll
        for (int it = 0; it < 2; it++) {
            int f = tid + it * 256;
            int k = f >> 5, n4 = (f & 31) << 2;
            int o = k * SB + n4;
            float4 v = *(const float4*)&Whi[(size_t)(kt + k) * C + bn + n4];
            *(float4*)&Bhi[o] = v;
            if (NSPLIT == 3) {
                float4 l = *(const float4*)&Wlo[(size_t)(kt + k) * C + bn + n4];
                *(float4*)&Blo[o] = l;
            }
        }
        __syncthreads();
#pragma unroll
        for (int kk = 0; kk < 16; kk += 8) {
            uint32_t ah[2][4], al[2][4];
#pragma unroll
            for (int mt = 0; mt < 2; mt++) {
                int mr = wm * 32 + mt * 16 + (lane >> 2);
                int kc = kk + (lane & 3);
                ah[mt][0] = __float_as_uint(Ahi[mr * SA + kc]);
                ah[mt][1] = __float_as_uint(Ahi[(mr + 8) * SA + kc]);
                ah[mt][2] = __float_as_uint(Ahi[mr * SA + kc + 4]);
                ah[mt][3] = __float_as_uint(Ahi[(mr + 8) * SA + kc + 4]);
                if (NSPLIT == 3) {
                    al[mt][0] = __float_as_uint(Alo[mr * SA + kc]);
                    al[mt][1] = __float_as_uint(Alo[(mr + 8) * SA + kc]);
                    al[mt][2] = __float_as_uint(Alo[mr * SA + kc + 4]);
                    al[mt][3] = __float_as_uint(Alo[(mr + 8) * SA + kc + 4]);
                }
            }
#pragma unroll
            for (int nt = 0; nt < 8; nt++) {
                int nc = wn * 64 + nt * 8 + (lane >> 2);
                int kr = kk + (lane & 3);
                uint32_t bh[2] = { __float_as_uint(Bhi[kr * SB + nc]),
                                   __float_as_uint(Bhi[(kr + 4) * SB + nc]) };
#pragma unroll
                for (int mt = 0; mt < 2; mt++) mma8(acc[mt][nt], ah[mt], bh);
                if (NSPLIT == 3) {
                    uint32_t bl[2] = { __float_as_uint(Blo[kr * SB + nc]),
                                       __float_as_uint(Blo[(kr + 4) * SB + nc]) };
#pragma unroll
                    for (int mt = 0; mt < 2; mt++) {
                        mma8(acc[mt][nt], ah[mt], bl);
                        mma8(acc[mt][nt], al[mt], bh);
                    }
                }
            }
        }
        __syncthreads();
    }
#pragma unroll
    for (int mt = 0; mt < 2; mt++)
#pragma unroll
        for (int rr = 0; rr < 2; rr++) {
            int row = bm + wm * 32 + mt * 16 + (lane >> 2) + rr * 8;
            if (row < NN) {
                float dv = g_dinv[row];
                const float* wd = nullptr;
                if (ONEHOT) wd = Wraw + (size_t)(K + deg[row]) * C + bn;
#pragma unroll
                for (int nt = 0; nt < 8; nt++) {
                    int col = wn * 64 + nt * 8 + (lane & 3) * 2;
                    float v0 = acc[mt][nt][rr * 2 + 0];
                    float v1 = acc[mt][nt][rr * 2 + 1];
                    if (ONEHOT) { v0 += wd[col]; v1 += wd[col + 1]; }
                    *(float2*)&out[(size_t)row * C + bn + col] = make_float2(v0 * dv, v1 * dv);
                }
            }
        }
}

// ---------------- aggregation ----------------
template <int C, int RELU>
__global__ void agg_kernel(const float* __restrict__ g, const float* __restrict__ bias,
                           float* __restrict__ out) {
    int warp = (blockIdx.x * blockDim.x + threadIdx.x) >> 5;
    int lane = threadIdx.x & 31;
    if (warp >= NN) return;
    int n = warp;
    const int V = C / 4;
    const float4* g4 = (const float4*)g;
    float4 a0 = g4[(size_t)n * V + lane];
    float4 a1 = make_float4(0.f, 0.f, 0.f, 0.f);
    if (C == 256) a1 = g4[(size_t)n * V + 32 + lane];
    int beg = g_rowptr[n], end = g_rowptr[n + 1];
    for (int p = beg; p < end; ++p) {
        int s = g_csr[p];
        float4 b0 = g4[(size_t)s * V + lane];
        a0.x += b0.x; a0.y += b0.y; a0.z += b0.z; a0.w += b0.w;
        if (C == 256) {
            float4 b1v = g4[(size_t)s * V + 32 + lane];
            a1.x += b1v.x; a1.y += b1v.y; a1.z += b1v.z; a1.w += b1v.w;
        }
    }
    float dv = g_dinv[n];
    const float4* bias4 = (const float4*)bias;
    float4 bb = bias4[lane];
    a0.x = a0.x * dv + bb.x; a0.y = a0.y * dv + bb.y;
    a0.z = a0.z * dv + bb.z; a0.w = a0.w * dv + bb.w;
    if (RELU) {
        a0.x = fmaxf(a0.x, 0.f); a0.y = fmaxf(a0.y, 0.f);
        a0.z = fmaxf(a0.z, 0.f); a0.w = fmaxf(a0.w, 0.f);
    }
    ((float4*)out)[(size_t)n * V + lane] = a0;
    if (C == 256) {
        float4 b2 = bias4[32 + lane];
        a1.x = a1.x * dv + b2.x; a1.y = a1.y * dv + b2.y;
        a1.z = a1.z * dv + b2.z; a1.w = a1.w * dv + b2.w;
        if (RELU) {
            a1.x = fmaxf(a1.x, 0.f); a1.y = fmaxf(a1.y, 0.f);
            a1.z = fmaxf(a1.z, 0.f); a1.w = fmaxf(a1.w, 0.f);
        }
        ((float4*)out)[(size_t)n * V + 32 + lane] = a1;
    }
}

// ---------------- fused ep1 + U precompute ----------------
// 256 threads, 32 nodes/block. Computes ep1 score -> amax, and Ut[k][n] = z@p2w1.
__global__ void __launch_bounds__(256) ep1u_kernel(
    const float* __restrict__ z,
    const float* __restrict__ p1w1, const float* __restrict__ p1b1,
    const float* __restrict__ p1w2, const float* __restrict__ p1b2,
    const float* __restrict__ p2w1) {
    __shared__ float zs[32][128];
    __shared__ float sm2[64][33];
    int tid = threadIdx.x;
    int grp = tid >> 6, k = tid & 63;
    int n0 = blockIdx.x * 32;
    for (int i = tid; i < 32 * 128; i += 256) {
        int gi = n0 * 128 + i;
        ((float*)zs)[i] = (gi < NN * 128) ? z[gi] : 0.f;
    }
    __syncthreads();
    float bk = p1b1[k];
    float acc1[8], accu[8];
#pragma unroll
    for (int nn = 0; nn < 8; nn++) { acc1[nn] = bk; accu[nn] = 0.f; }
#pragma unroll 4
    for (int j = 0; j < 128; j++) {
        float w1v = p1w1[j * 64 + k];
        float w2v = p2w1[j * 64 + k];
#pragma unroll
        for (int nn = 0; nn < 8; nn++) {
            float zv = zs[grp * 8 + nn][j];
            acc1[nn] += zv * w1v;
            accu[nn] += zv * w2v;
        }
    }
    // ep1 scores: sm2[k][node] = relu(h)*w2[k]
    float wk = p1w2[k];
#pragma unroll
    for (int nn = 0; nn < 8; nn++) sm2[k][grp * 8 + nn] = fmaxf(acc1[nn], 0.f) * wk;
    __syncthreads();
    {
        int nd = tid >> 3, q = tid & 7;
        float s = 0.f;
#pragma unroll
        for (int m = 0; m < 8; m++) s += sm2[q * 8 + m][nd];
        for (int o = 4; o; o >>= 1) s += __shfl_down_sync(~0u, s, o, 8);
        if (q == 0 && n0 + nd < NN) atomicMax(&g_amax[0], packmax(s + p1b2[0], n0 + nd));
    }
    __syncthreads();
    // stage U for coalesced transposed write
#pragma unroll
    for (int nn = 0; nn < 8; nn++) sm2[k][grp * 8 + nn] = accu[nn];
    __syncthreads();
    for (int i = tid; i < 64 * 32; i += 256) {
        int row = i >> 5, col = i & 31;
        if (n0 + col < NN) g_Ut[(size_t)row * NN + n0 + col] = sm2[row][col];
    }
}

__global__ void fswap_kernel(FwdPlan p) {
    for (int t = 0; t < TSTEPS; t++) do_swap(p.i1[t], p.i2[t], p.coin[t]);
}

// scores2 + fused c-computation + fused swap (last block)
__global__ void scores2_kernel(const float* __restrict__ z, const float* __restrict__ w1,
                               const float* __restrict__ b1, const float* __restrict__ w2,
                               const float* __restrict__ b2, int coin) {
    __shared__ float z01[256];
    __shared__ float cs[64], ws[64];
    __shared__ unsigned long long red[256];
    int tid = threadIdx.x;
    int i1 = unpack_idx(g_amax[0]);
    int e10 = g_ei[i1], e11 = g_ei[EE + i1];
    if (tid < 128) z01[tid] = z[(size_t)e10 * 128 + tid];
    else           z01[tid] = z[(size_t)e11 * 128 + (tid - 128)];
    __syncthreads();
    if (tid < 64) {
        float c = b1[tid];
#pragma unroll 8
        for (int j = 0; j < 256; j++) c += z01[j] * w1[(size_t)(128 + j) * 64 + tid];
        cs[tid] = c; ws[tid] = w2[tid];
    }
    __syncthreads();
    int n = blockIdx.x * 256 + tid;
    unsigned long long key = 0ULL;
    if (n < NN) {
        float s = b2[0];
#pragma unroll
        for (int k = 0; k < 64; k++) {
            float u = g_Ut[(size_t)k * NN + n] + cs[k];
            s += fmaxf(u, 0.f) * ws[k];
        }
        key = packmax(s, n);
    }
    red[tid] = key;
    __syncthreads();
    for (int off = 128; off; off >>= 1) {
        if (tid < off) { unsigned long long o = red[tid + off]; if (o > red[tid]) red[tid] = o; }
        __syncthreads();
    }
    if (tid == 0) {
        atomicMax(&g_amax[1], red[0]);
        __threadfence();
        int t = atomicAdd(&g_done, 1);
        if (t == (int)gridDim.x - 1) {
            g_done = 0;
            int a = unpack_idx(g_amax[0]);
            int b = unpack_idx(g_amax[1]);
            do_swap(a, b, coin);
            g_amax[1] = 0ULL;
        }
    }
}

__global__ void eiout_kernel(float* __restrict__ out) {
    int i = blockIdx.x * blockDim.x + threadIdx.x;
    if (i < 2 * EE) out[(size_t)NN * FF + i] = (float)g_ei[i];
}

// ---------------- host-side JAX threefry (partitionable semantics) ----------------
static inline uint32_t rotl32(uint32_t x, int d) { return (x << d) | (x >> (32 - d)); }
static void tf2x32(uint32_t k0, uint32_t k1, uint32_t x0, uint32_t x1,
                   uint32_t& o0, uint32_t& o1) {
    uint32_t ks2 = k0 ^ k1 ^ 0x1BD11BDAu;
    static const int RA[4] = {13, 15, 26, 6}, RB[4] = {17, 29, 16, 24};
    x0 += k0; x1 += k1;
#define RND4(R) for (int i = 0; i < 4; i++) { x0 += x1; x1 = rotl32(x1, R[i]); x1 ^= x0; }
    RND4(RA) x0 += k1;  x1 += ks2 + 1;
    RND4(RB) x0 += ks2; x1 += k0 + 2;
    RND4(RA) x0 += k0;  x1 += k1 + 3;
    RND4(RB) x0 += k1;  x1 += ks2 + 4;
    RND4(RA) x0 += ks2; x1 += k0 + 5;
#undef RND4
    o0 = x0; o1 = x1;
}
struct KP { uint32_t a, b; };
static KP kfold(KP k, uint32_t t) { KP r; tf2x32(k.a, k.b, 0u, t, r.a, r.b); return r; }
static void ksplit(KP k, KP& A, KP& B) {
    tf2x32(k.a, k.b, 0u, 0u, A.a, A.b);
    tf2x32(k.a, k.b, 0u, 1u, B.a, B.b);
}
static inline uint32_t kbits(KP k, uint32_t i) {
    uint32_t o0, o1; tf2x32(k.a, k.b, 0u, i, o0, o1); return o0 ^ o1;
}
static bool kbern(KP k) { return (kbits(k, 0u) >> 31) == 0; }

static void perm_first2(KP key, int& i1, int& i2) {
    KP kA, s1, kB, s2;
    ksplit(key, kA, s1);
    ksplit(kA, kB, s2);
    std::vector<uint32_t> b1(EE), b2(EE);
    for (int i = 0; i < EE; i++) b1[i] = kbits(s1, (uint32_t)i);
    for (int i = 0; i < EE; i++) b2[i] = kbits(s2, (uint32_t)i);
    uint64_t m0 = ~0ULL, m1 = ~0ULL;
    for (int p = 0; p < EE; p++) {
        uint64_t v = ((uint64_t)b2[p] << 32) | (uint32_t)p;
        if (v < m0) { m1 = m0; m0 = v; }
        else if (v < m1) { m1 = v; }
    }
    int p0 = (int)(uint32_t)(m0 & 0xFFFFFFFFu);
    int p1 = (int)(uint32_t)(m1 & 0xFFFFFFFFu);
    std::vector<uint64_t> s(EE);
    for (int j = 0; j < EE; j++) s[j] = ((uint64_t)b1[j] << 32) | (uint32_t)j;
    std::nth_element(s.begin(), s.begin() + p0, s.end());
    i1 = (int)(uint32_t)(s[p0] & 0xFFFFFFFFu);
    std::nth_element(s.begin(), s.begin() + p1, s.end());
    i2 = (int)(uint32_t)(s[p1] & 0xFFFFFFFFu);
}

extern "C" void kernel_launch(void* const* d_in, const int* in_sizes, int n_in,
                              void* d_out, int out_size) {
    int base = n_in - 16;
    const float* x    = (const float*)d_in[0];
    const int* ei_in  = (const int*)d_in[1];
    const int* dset   = (const int*)d_in[2];
    const float* ew1  = (const float*)d_in[base + 0];
    const float* eb1  = (const float*)d_in[base + 1];
    const float* ew2  = (const float*)d_in[base + 2];
    const float* eb2  = (const float*)d_in[base + 3];
    const float* dw1  = (const float*)d_in[base + 4];
    const float* db1  = (const float*)d_in[base + 5];
    const float* dw2  = (const float*)d_in[base + 6];
    const float* db2  = (const float*)d_in[base + 7];
    const float* p1w1 = (const float*)d_in[base + 8];
    const float* p1b1 = (const float*)d_in[base + 9];
    const float* p1w2 = (const float*)d_in[base + 10];
    const float* p1b2 = (const float*)d_in[base + 11];
    const float* p2w1 = (const float*)d_in[base + 12];
    const float* p2b1 = (const float*)d_in[base + 13];
    const float* p2w2 = (const float*)d_in[base + 14];
    const float* p2b2 = (const float*)d_in[base + 15];
    float* out = (float*)d_out;

    // ---- host plan (pure PRNG constants, untimed) ----
    FwdPlan plan;
    int rcoin[TSTEPS];
    for (int t = 0; t < TSTEPS; t++) {
        KP kt = kfold({0u, 1u}, (uint32_t)t);
        KP k1, k2;
        ksplit(kt, k1, k2);
        plan.coin[t] = kbern(k2) ? 1 : 0;
        perm_first2(k1, plan.i1[t], plan.i2[t]);
        rcoin[t] = kbern(kfold({0u, 2u}, (uint32_t)t)) ? 1 : 0;
    }

    int* dev_ei = nullptr; float* lin = nullptr; float* hbuf = nullptr; float* zb = nullptr;
    float* whi = nullptr; float* wlo = nullptr;
    cudaGetSymbolAddress((void**)&dev_ei, g_ei);
    cudaGetSymbolAddress((void**)&lin, g_lin);
    cudaGetSymbolAddress((void**)&hbuf, g_hbuf);
    cudaGetSymbolAddress((void**)&zb, g_z);
    cudaGetSymbolAddress((void**)&whi, g_Whi);
    cudaGetSymbolAddress((void**)&wlo, g_Wlo);

    const int WSZ = 32768;  // 128x256 or 256x128
    // ---- W precompute: encoder split (3x), decoder round (1x) ----
    wsplit_kernel<<<(WSZ + 255) / 256, 256>>>(ew1, WSZ, whi, wlo);                 // enc1 (rows 0..127)
    wsplit_kernel<<<(WSZ + 255) / 256, 256>>>(ew2, WSZ, whi + WSZ, wlo + WSZ);     // enc2
    wround_kernel<<<(WSZ + 255) / 256, 256>>>(dw1, WSZ, whi + 2 * WSZ);            // dec1 (rows 0..127)
    wround_kernel<<<(WSZ + 255) / 256, 256>>>(dw2, WSZ, whi + 3 * WSZ);            // dec2

    // ---- original-graph CSR + dinv ----
    copy_ei_kernel<<<(2 * EE + 255) / 256, 256>>>(ei_in);
    hist_kernel<<<(EE + 255) / 256, 256>>>(ei_in + EE);
    scanA_kernel<<<SCAN_NB, 256>>>();
    scanB_kernel<<<1, SCAN_NB>>>();
    scanC_kernel<<<SCAN_NB, 256>>>();
    fill_kernel<<<(EE + 255) / 256, 256>>>(ei_in);

    dim3 g2(2, (NN + 127) / 128), g1(1, (NN + 127) / 128);
    // ---- encoder (3xTF32) ----
    mma_gemm_kernel<1, 3><<<g2, 256>>>(x, 128, whi, wlo, ew1, 256, dset, lin);
    agg_kernel<256, 1><<<(NN * 32 + 255) / 256, 256>>>(lin, eb1, hbuf);
    mma_gemm_kernel<0, 3><<<g1, 256>>>(hbuf, 256, whi + WSZ, wlo + WSZ, ew2, 128, nullptr, lin);
    agg_kernel<128, 0><<<(NN * 32 + 255) / 256, 256>>>(lin, eb2, zb);

    // ---- predictors + forward swaps ----
    ep1u_kernel<<<(NN + 31) / 32, 256>>>(zb, p1w1, p1b1, p1w2, p1b2, p2w1);
    fswap_kernel<<<1, 1>>>(plan);

    // ---- reverse process (swap fused into scores2 last block) ----
    for (int t = 0; t < TSTEPS; t++)
        scores2_kernel<<<(NN + 255) / 256, 256>>>(zb, p2w1, p2b1, p2w2, p2b2, rcoin[t]);

    // ---- final-graph CSR + dinv ----
    zero_cnt_kernel<<<(NN + 255) / 256, 256>>>();
    hist_kernel<<<(EE + 255) / 256, 256>>>(dev_ei + EE);
    scanA_kernel<<<SCAN_NB, 256>>>();
    scanB_kernel<<<1, SCAN_NB>>>();
    scanC_kernel<<<SCAN_NB, 256>>>();
    fill_kernel<<<(EE + 255) / 256, 256>>>(dev_ei);

    // ---- decoder (1xTF32) ----
    mma_gemm_kernel<1, 1><<<g2, 256>>>(zb, 128, whi + 2 * WSZ, nullptr, dw1, 256, dset, lin);
    agg_kernel<256, 1><<<(NN * 32 + 255) / 256, 256>>>(lin, db1, hbuf);
    mma_gemm_kernel<0, 1><<<g1, 256>>>(hbuf, 256, whi + 3 * WSZ, nullptr, dw2, 128, nullptr, lin);
    agg_kernel<128, 0><<<(NN * 32 + 255) / 256, 256>>>(lin, db2, out);

    // ---- emit final edge index as floats ----
    eiout_kernel<<<(2 * EE + 255) / 256, 256>>>(out);
}

// round 7
// speedup vs baseline: 2.2637x; 1.2019x over previous
#include <cuda_runtime.h>
#include <stdint.h>
#include <vector>
#include <algorithm>

#define NN 50000
#define EE 800000
#define FF 128
#define TSTEPS 5
#define SCAN_NB 128

// ---------------- static device buffers ----------------
__device__ int   g_ei[2 * EE];
__device__ int   g_cnt[NN];
__device__ int   g_rowptr[NN + 1];
__device__ int   g_cursor[NN];
__device__ int   g_csr[EE];
__device__ int   g_bsum[SCAN_NB];
__device__ int   g_done;
__device__ float g_dinv[NN];
__device__ float g_lin[(size_t)NN * 256];
__device__ float g_hbuf[(size_t)NN * 256];
__device__ float g_z[(size_t)NN * 128];
__device__ float g_Ut[(size_t)64 * NN];
__device__ float g_Whi[4 * 32768];
__device__ unsigned long long g_amax[2];

struct FwdPlan { int i1[TSTEPS]; int i2[TSTEPS]; int coin[TSTEPS]; };

__device__ __forceinline__ float tf32rna(float x) {
    uint32_t u; asm("cvt.rna.tf32.f32 %0, %1;" : "=r"(u) : "f"(x));
    return __uint_as_float(u);
}
__device__ __forceinline__ unsigned long long packmax(float v, int idx) {
    unsigned u = __float_as_uint(v);
    u ^= ((unsigned)((int)u >> 31)) | 0x80000000u;
    return ((unsigned long long)u << 32) | (unsigned)(0xFFFFFFFFu - (unsigned)idx);
}
__device__ __forceinline__ int unpack_idx(unsigned long long k) {
    return (int)(0xFFFFFFFFu - (unsigned)(k & 0xFFFFFFFFu));
}
__device__ __forceinline__ void do_swap(int i1, int i2, int coin) {
    int a = g_ei[i1], b = g_ei[EE + i1];
    int c = g_ei[i2], d = g_ei[EE + i2];
    int n10, n11, n20, n21;
    if (coin) { n10 = a; n11 = d; n20 = c; n21 = b; }
    else      { n10 = a; n11 = c; n20 = b; n21 = d; }
    g_ei[i1] = n10; g_ei[EE + i1] = n11;
    g_ei[i2] = n20; g_ei[EE + i2] = n21;
}

// ---------------- W rounding: all 4 weight matrices in one launch ----------------
__global__ void wround4_kernel(const float* __restrict__ w0, const float* __restrict__ w1,
                               const float* __restrict__ w2, const float* __restrict__ w3) {
    int i = blockIdx.x * blockDim.x + threadIdx.x;
    int seg = i >> 15, off = i & 32767;
    const float* src = (seg == 0) ? w0 : (seg == 1) ? w1 : (seg == 2) ? w2 : w3;
    if (i < 4 * 32768) g_Whi[i] = tf32rna(src[off]);
}

// ---------------- graph structure ----------------
__global__ void zero_cnt_kernel() {
    int i = blockIdx.x * blockDim.x + threadIdx.x;
    if (i < NN) g_cnt[i] = 0;
    if (i == 0) { g_amax[0] = 0ULL; g_amax[1] = 0ULL; g_done = 0; }
}
// copy ei into g_ei AND histogram dst half in the same pass
__global__ void copyhist_kernel(const int* __restrict__ ei) {
    int i = blockIdx.x * blockDim.x + threadIdx.x;
    if (i < 2 * EE) {
        int v = ei[i];
        g_ei[i] = v;
        if (i >= EE) atomicAdd(&g_cnt[v], 1);
    }
}
__global__ void hist_kernel(const int* __restrict__ dst) {
    int e = blockIdx.x * blockDim.x + threadIdx.x;
    if (e < EE) atomicAdd(&g_cnt[dst[e]], 1);
}
__global__ void scanA_kernel() {
    const int CH = (NN + SCAN_NB - 1) / SCAN_NB;
    const int TC = (CH + 255) / 256;
    int b = blockIdx.x, t = threadIdx.x;
    int beg = b * CH;
    int s = 0;
#pragma unroll
    for (int i = 0; i < TC; i++) {
        int n = beg + t * TC + i;
        if (n < beg + CH && n < NN) s += g_cnt[n];
    }
    __shared__ int sm[8];
    for (int o = 16; o; o >>= 1) s += __shfl_down_sync(~0u, s, o);
    if ((t & 31) == 0) sm[t >> 5] = s;
    __syncthreads();
    if (t < 8) {
        int v = sm[t];
        for (int o = 4; o; o >>= 1) v += __shfl_down_sync(0xffu, v, o);
        if (t == 0) g_bsum[b] = v;
    }
}
__global__ void scanB_kernel() {
    int t = threadIdx.x;
    int v = g_bsum[t];
    int x = v;
    for (int o = 1; o < 32; o <<= 1) {
        int y = __shfl_up_sync(~0u, x, o);
        if ((t & 31) >= o) x += y;
    }
    __shared__ int ws[4];
    if ((t & 31) == 31) ws[t >> 5] = x;
    __syncthreads();
    int add = 0;
#pragma unroll
    for (int wI = 0; wI < 4; wI++) if (wI < (t >> 5)) add += ws[wI];
    g_bsum[t] = x + add - v;
}
__global__ void scanC_kernel() {
    const int CH = (NN + SCAN_NB - 1) / SCAN_NB;
    const int TC = (CH + 255) / 256;
    int b = blockIdx.x, t = threadIdx.x;
    int beg = b * CH;
    int c[TC]; int s = 0;
#pragma unroll
    for (int i = 0; i < TC; i++) {
        int n = beg + t * TC + i;
        c[i] = (n < beg + CH && n < NN) ? g_cnt[n] : 0;
        s += c[i];
    }
    int x = s;
    for (int o = 1; o < 32; o <<= 1) {
        int y = __shfl_up_sync(~0u, x, o);
        if ((t & 31) >= o) x += y;
    }
    __shared__ int ws[8];
    if ((t & 31) == 31) ws[t >> 5] = x;
    __syncthreads();
    int add = 0;
#pragma unroll
    for (int wI = 0; wI < 8; wI++) if (wI < (t >> 5)) add += ws[wI];
    int run = g_bsum[b] + x + add - s;
#pragma unroll
    for (int i = 0; i < TC; i++) {
        int n = beg + t * TC + i;
        if (n < beg + CH && n < NN) {
            g_rowptr[n] = run; g_cursor[n] = run;
            float df = (float)(c[i] + 1);
            float r = rsqrtf(df);
            r = r * (1.5f - 0.5f * df * r * r);
            g_dinv[n] = r;
            run += c[i];
        }
    }
    if (b == 0 && t == 0) g_rowptr[NN] = EE;
}
__global__ void fill_kernel(const int* __restrict__ ei) {
    int e = blockIdx.x * blockDim.x + threadIdx.x;
    if (e < EE) {
        int s = ei[e], d = ei[EE + e];
        int pos = atomicAdd(&g_cursor[d], 1);
        g_csr[pos] = s;
    }
}

// ---------------- tensor-core GEMM (1xTF32) ----------------
// out[m][c] = dinv[m]*(tf32(A[m]) @ tf32(W) + Wd[K+deg[m]])
__device__ __forceinline__ void mma8(float d[4], const uint32_t a[4], const uint32_t b[2]) {
    asm("mma.sync.aligned.m16n8k8.row.col.f32.tf32.tf32.f32 "
        "{%0,%1,%2,%3}, {%4,%5,%6,%7}, {%8,%9}, {%0,%1,%2,%3};"
        : "+f"(d[0]), "+f"(d[1]), "+f"(d[2]), "+f"(d[3])
        : "r"(a[0]), "r"(a[1]), "r"(a[2]), "r"(a[3]), "r"(b[0]), "r"(b[1]));
}

template <int ONEHOT>
__global__ void __launch_bounds__(256) mma_gemm_kernel(
    const float* __restrict__ A, int K,
    const float* __restrict__ Whi, const float* __restrict__ Wraw, int C,
    const int* __restrict__ deg, float* __restrict__ out) {
    const int SA = 20;
    const int SB = 136;
    __shared__ float Ahi[128 * SA];
    __shared__ float Bhi[16 * SB];
    int bm = blockIdx.y * 128, bn = blockIdx.x * 128;
    int tid = threadIdx.x, lane = tid & 31, w = tid >> 5;
    int wm = w >> 1, wn = w & 1;

    float acc[2][8][4];
#pragma unroll
    for (int mt = 0; mt < 2; mt++)
#pragma unroll
        for (int nt = 0; nt < 8; nt++)
#pragma unroll
            for (int r = 0; r < 4; r++) acc[mt][nt][r] = 0.f;

    for (int kt = 0; kt < K; kt += 16) {
#pragma unroll
        for (int it = 0; it < 2; it++) {
            int f = tid + it * 256;
            int m = f >> 2, k4 = (f & 3) << 2;
            float4 v = make_float4(0.f, 0.f, 0.f, 0.f);
            if (bm + m < NN) v = *(const float4*)&A[(size_t)(bm + m) * K + kt + k4];
            int o = m * SA + k4;
            Ahi[o] = tf32rna(v.x); Ahi[o + 1] = tf32rna(v.y);
            Ahi[o + 2] = tf32rna(v.z); Ahi[o + 3] = tf32rna(v.w);
        }
#pragma unroll
        for (int it = 0; it < 2; it++) {
            int f = tid + it * 256;
            int k = f >> 5, n4 = (f & 31) << 2;
            float4 v = *(const float4*)&Whi[(size_t)(kt + k) * C + bn + n4];
            *(float4*)&Bhi[k * SB + n4] = v;
        }
        __syncthreads();
#pragma unroll
        for (int kk = 0; kk < 16; kk += 8) {
            uint32_t ah[2][4];
#pragma unroll
            for (int mt = 0; mt < 2; mt++) {
                int mr = wm * 32 + mt * 16 + (lane >> 2);
                int kc = kk + (lane & 3);
                ah[mt][0] = __float_as_uint(Ahi[mr * SA + kc]);
                ah[mt][1] = __float_as_uint(Ahi[(mr + 8) * SA + kc]);
                ah[mt][2] = __float_as_uint(Ahi[mr * SA + kc + 4]);
                ah[mt][3] = __float_as_uint(Ahi[(mr + 8) * SA + kc + 4]);
            }
#pragma unroll
            for (int nt = 0; nt < 8; nt++) {
                int nc = wn * 64 + nt * 8 + (lane >> 2);
                int kr = kk + (lane & 3);
                uint32_t bh[2] = { __float_as_uint(Bhi[kr * SB + nc]),
                                   __float_as_uint(Bhi[(kr + 4) * SB + nc]) };
#pragma unroll
                for (int mt = 0; mt < 2; mt++) mma8(acc[mt][nt], ah[mt], bh);
            }
        }
        __syncthreads();
    }
#pragma unroll
    for (int mt = 0; mt < 2; mt++)
#pragma unroll
        for (int rr = 0; rr < 2; rr++) {
            int row = bm + wm * 32 + mt * 16 + (lane >> 2) + rr * 8;
            if (row < NN) {
                float dv = g_dinv[row];
                const float* wd = nullptr;
                if (ONEHOT) wd = Wraw + (size_t)(K + deg[row]) * C + bn;
#pragma unroll
                for (int nt = 0; nt < 8; nt++) {
                    int col = wn * 64 + nt * 8 + (lane & 3) * 2;
                    float v0 = acc[mt][nt][rr * 2 + 0];
                    float v1 = acc[mt][nt][rr * 2 + 1];
                    if (ONEHOT) { v0 += wd[col]; v1 += wd[col + 1]; }
                    *(float2*)&out[(size_t)row * C + bn + col] = make_float2(v0 * dv, v1 * dv);
                }
            }
        }
}

// ---------------- aggregation ----------------
template <int C, int RELU>
__global__ void agg_kernel(const float* __restrict__ g, const float* __restrict__ bias,
                           float* __restrict__ out) {
    int warp = (blockIdx.x * blockDim.x + threadIdx.x) >> 5;
    int lane = threadIdx.x & 31;
    if (warp >= NN) return;
    int n = warp;
    const int V = C / 4;
    const float4* g4 = (const float4*)g;
    float4 a0 = g4[(size_t)n * V + lane];
    float4 a1 = make_float4(0.f, 0.f, 0.f, 0.f);
    if (C == 256) a1 = g4[(size_t)n * V + 32 + lane];
    int beg = g_rowptr[n], end = g_rowptr[n + 1];
    for (int p = beg; p < end; ++p) {
        int s = g_csr[p];
        float4 b0 = g4[(size_t)s * V + lane];
        a0.x += b0.x; a0.y += b0.y; a0.z += b0.z; a0.w += b0.w;
        if (C == 256) {
            float4 b1v = g4[(size_t)s * V + 32 + lane];
            a1.x += b1v.x; a1.y += b1v.y; a1.z += b1v.z; a1.w += b1v.w;
        }
    }
    float dv = g_dinv[n];
    const float4* bias4 = (const float4*)bias;
    float4 bb = bias4[lane];
    a0.x = a0.x * dv + bb.x; a0.y = a0.y * dv + bb.y;
    a0.z = a0.z * dv + bb.z; a0.w = a0.w * dv + bb.w;
    if (RELU) {
        a0.x = fmaxf(a0.x, 0.f); a0.y = fmaxf(a0.y, 0.f);
        a0.z = fmaxf(a0.z, 0.f); a0.w = fmaxf(a0.w, 0.f);
    }
    ((float4*)out)[(size_t)n * V + lane] = a0;
    if (C == 256) {
        float4 b2 = bias4[32 + lane];
        a1.x = a1.x * dv + b2.x; a1.y = a1.y * dv + b2.y;
        a1.z = a1.z * dv + b2.z; a1.w = a1.w * dv + b2.w;
        if (RELU) {
            a1.x = fmaxf(a1.x, 0.f); a1.y = fmaxf(a1.y, 0.f);
            a1.z = fmaxf(a1.z, 0.f); a1.w = fmaxf(a1.w, 0.f);
        }
        ((float4*)out)[(size_t)n * V + 32 + lane] = a1;
    }
}

// ---------------- fused ep1 + U precompute ----------------
__global__ void __launch_bounds__(256) ep1u_kernel(
    const float* __restrict__ z,
    const float* __restrict__ p1w1, const float* __restrict__ p1b1,
    const float* __restrict__ p1w2, const float* __restrict__ p1b2,
    const float* __restrict__ p2w1) {
    __shared__ float zs[32][128];
    __shared__ float sm2[64][33];
    int tid = threadIdx.x;
    int grp = tid >> 6, k = tid & 63;
    int n0 = blockIdx.x * 32;
    for (int i = tid; i < 32 * 128; i += 256) {
        int gi = n0 * 128 + i;
        ((float*)zs)[i] = (gi < NN * 128) ? z[gi] : 0.f;
    }
    __syncthreads();
    float bk = p1b1[k];
    float acc1[8], accu[8];
#pragma unroll
    for (int nn = 0; nn < 8; nn++) { acc1[nn] = bk; accu[nn] = 0.f; }
#pragma unroll 4
    for (int j = 0; j < 128; j++) {
        float w1v = p1w1[j * 64 + k];
        float w2v = p2w1[j * 64 + k];
#pragma unroll
        for (int nn = 0; nn < 8; nn++) {
            float zv = zs[grp * 8 + nn][j];
            acc1[nn] += zv * w1v;
            accu[nn] += zv * w2v;
        }
    }
    float wk = p1w2[k];
#pragma unroll
    for (int nn = 0; nn < 8; nn++) sm2[k][grp * 8 + nn] = fmaxf(acc1[nn], 0.f) * wk;
    __syncthreads();
    {
        int nd = tid >> 3, q = tid & 7;
        float s = 0.f;
#pragma unroll
        for (int m = 0; m < 8; m++) s += sm2[q * 8 + m][nd];
        for (int o = 4; o; o >>= 1) s += __shfl_down_sync(~0u, s, o, 8);
        if (q == 0 && n0 + nd < NN) atomicMax(&g_amax[0], packmax(s + p1b2[0], n0 + nd));
    }
    __syncthreads();
#pragma unroll
    for (int nn = 0; nn < 8; nn++) sm2[k][grp * 8 + nn] = accu[nn];
    __syncthreads();
    for (int i = tid; i < 64 * 32; i += 256) {
        int row = i >> 5, col = i & 31;
        if (n0 + col < NN) g_Ut[(size_t)row * NN + n0 + col] = sm2[row][col];
    }
}

__global__ void fswap_kernel(FwdPlan p) {
    for (int t = 0; t < TSTEPS; t++) do_swap(p.i1[t], p.i2[t], p.coin[t]);
}

// scores2 + fused c-computation + fused swap (last block)
__global__ void scores2_kernel(const float* __restrict__ z, const float* __restrict__ w1,
                               const float* __restrict__ b1, const float* __restrict__ w2,
                               const float* __restrict__ b2, int coin) {
    __shared__ float z01[256];
    __shared__ float cs[64], ws[64];
    __shared__ unsigned long long red[256];
    int tid = threadIdx.x;
    int i1 = unpack_idx(g_amax[0]);
    int e10 = g_ei[i1], e11 = g_ei[EE + i1];
    if (tid < 128) z01[tid] = z[(size_t)e10 * 128 + tid];
    else           z01[tid] = z[(size_t)e11 * 128 + (tid - 128)];
    __syncthreads();
    if (tid < 64) {
        float c = b1[tid];
#pragma unroll 8
        for (int j = 0; j < 256; j++) c += z01[j] * w1[(size_t)(128 + j) * 64 + tid];
        cs[tid] = c; ws[tid] = w2[tid];
    }
    __syncthreads();
    int n = blockIdx.x * 256 + tid;
    unsigned long long key = 0ULL;
    if (n < NN) {
        float s = b2[0];
#pragma unroll
        for (int k = 0; k < 64; k++) {
            float u = g_Ut[(size_t)k * NN + n] + cs[k];
            s += fmaxf(u, 0.f) * ws[k];
        }
        key = packmax(s, n);
    }
    red[tid] = key;
    __syncthreads();
    for (int off = 128; off; off >>= 1) {
        if (tid < off) { unsigned long long o = red[tid + off]; if (o > red[tid]) red[tid] = o; }
        __syncthreads();
    }
    if (tid == 0) {
        atomicMax(&g_amax[1], red[0]);
        __threadfence();
        int t = atomicAdd(&g_done, 1);
        if (t == (int)gridDim.x - 1) {
            g_done = 0;
            int a = unpack_idx(g_amax[0]);
            int b = unpack_idx(g_amax[1]);
            do_swap(a, b, coin);
            g_amax[1] = 0ULL;
        }
    }
}

__global__ void eiout_kernel(float* __restrict__ out) {
    int i = blockIdx.x * blockDim.x + threadIdx.x;
    if (i < 2 * EE) out[(size_t)NN * FF + i] = (float)g_ei[i];
}

// ---------------- host-side JAX threefry (partitionable semantics) ----------------
static inline uint32_t rotl32(uint32_t x, int d) { return (x << d) | (x >> (32 - d)); }
static void tf2x32(uint32_t k0, uint32_t k1, uint32_t x0, uint32_t x1,
                   uint32_t& o0, uint32_t& o1) {
    uint32_t ks2 = k0 ^ k1 ^ 0x1BD11BDAu;
    static const int RA[4] = {13, 15, 26, 6}, RB[4] = {17, 29, 16, 24};
    x0 += k0; x1 += k1;
#define RND4(R) for (int i = 0; i < 4; i++) { x0 += x1; x1 = rotl32(x1, R[i]); x1 ^= x0; }
    RND4(RA) x0 += k1;  x1 += ks2 + 1;
    RND4(RB) x0 += ks2; x1 += k0 + 2;
    RND4(RA) x0 += k0;  x1 += k1 + 3;
    RND4(RB) x0 += k1;  x1 += ks2 + 4;
    RND4(RA) x0 += ks2; x1 += k0 + 5;
#undef RND4
    o0 = x0; o1 = x1;
}
struct KP { uint32_t a, b; };
static KP kfold(KP k, uint32_t t) { KP r; tf2x32(k.a, k.b, 0u, t, r.a, r.b); return r; }
static void ksplit(KP k, KP& A, KP& B) {
    tf2x32(k.a, k.b, 0u, 0u, A.a, A.b);
    tf2x32(k.a, k.b, 0u, 1u, B.a, B.b);
}
static inline uint32_t kbits(KP k, uint32_t i) {
    uint32_t o0, o1; tf2x32(k.a, k.b, 0u, i, o0, o1); return o0 ^ o1;
}
static bool kbern(KP k) { return (kbits(k, 0u) >> 31) == 0; }

static void perm_first2(KP key, int& i1, int& i2) {
    KP kA, s1, kB, s2;
    ksplit(key, kA, s1);
    ksplit(kA, kB, s2);
    std::vector<uint32_t> b1(EE), b2(EE);
    for (int i = 0; i < EE; i++) b1[i] = kbits(s1, (uint32_t)i);
    for (int i = 0; i < EE; i++) b2[i] = kbits(s2, (uint32_t)i);
    uint64_t m0 = ~0ULL, m1 = ~0ULL;
    for (int p = 0; p < EE; p++) {
        uint64_t v = ((uint64_t)b2[p] << 32) | (uint32_t)p;
        if (v < m0) { m1 = m0; m0 = v; }
        else if (v < m1) { m1 = v; }
    }
    int p0 = (int)(uint32_t)(m0 & 0xFFFFFFFFu);
    int p1 = (int)(uint32_t)(m1 & 0xFFFFFFFFu);
    std::vector<uint64_t> s(EE);
    for (int j = 0; j < EE; j++) s[j] = ((uint64_t)b1[j] << 32) | (uint32_t)j;
    std::nth_element(s.begin(), s.begin() + p0, s.end());
    i1 = (int)(uint32_t)(s[p0] & 0xFFFFFFFFu);
    std::nth_element(s.begin(), s.begin() + p1, s.end());
    i2 = (int)(uint32_t)(s[p1] & 0xFFFFFFFFu);
}

extern "C" void kernel_launch(void* const* d_in, const int* in_sizes, int n_in,
                              void* d_out, int out_size) {
    int base = n_in - 16;
    const float* x    = (const float*)d_in[0];
    const int* ei_in  = (const int*)d_in[1];
    const int* dset   = (const int*)d_in[2];
    const float* ew1  = (const float*)d_in[base + 0];
    const float* eb1  = (const float*)d_in[base + 1];
    const float* ew2  = (const float*)d_in[base + 2];
    const float* eb2  = (const float*)d_in[base + 3];
    const float* dw1  = (const float*)d_in[base + 4];
    const float* db1  = (const float*)d_in[base + 5];
    const float* dw2  = (const float*)d_in[base + 6];
    const float* db2  = (const float*)d_in[base + 7];
    const float* p1w1 = (const float*)d_in[base + 8];
    const float* p1b1 = (const float*)d_in[base + 9];
    const float* p1w2 = (const float*)d_in[base + 10];
    const float* p1b2 = (const float*)d_in[base + 11];
    const float* p2w1 = (const float*)d_in[base + 12];
    const float* p2b1 = (const float*)d_in[base + 13];
    const float* p2w2 = (const float*)d_in[base + 14];
    const float* p2b2 = (const float*)d_in[base + 15];
    float* out = (float*)d_out;

    // ---- host plan (pure PRNG constants, untimed) ----
    FwdPlan plan;
    int rcoin[TSTEPS];
    for (int t = 0; t < TSTEPS; t++) {
        KP kt = kfold({0u, 1u}, (uint32_t)t);
        KP k1, k2;
        ksplit(kt, k1, k2);
        plan.coin[t] = kbern(k2) ? 1 : 0;
        perm_first2(k1, plan.i1[t], plan.i2[t]);
        rcoin[t] = kbern(kfold({0u, 2u}, (uint32_t)t)) ? 1 : 0;
    }

    int* dev_ei = nullptr; float* lin = nullptr; float* hbuf = nullptr; float* zb = nullptr;
    float* whi = nullptr;
    cudaGetSymbolAddress((void**)&dev_ei, g_ei);
    cudaGetSymbolAddress((void**)&lin, g_lin);
    cudaGetSymbolAddress((void**)&hbuf, g_hbuf);
    cudaGetSymbolAddress((void**)&zb, g_z);
    cudaGetSymbolAddress((void**)&whi, g_Whi);

    const int WSZ = 32768;
    // ---- W rounding (single launch for all 4 weight matrices) ----
    wround4_kernel<<<(4 * WSZ + 255) / 256, 256>>>(ew1, ew2, dw1, dw2);

    // ---- original-graph CSR + dinv (copy + hist fused) ----
    zero_cnt_kernel<<<(NN + 255) / 256, 256>>>();
    copyhist_kernel<<<(2 * EE + 255) / 256, 256>>>(ei_in);
    scanA_kernel<<<SCAN_NB, 256>>>();
    scanB_kernel<<<1, SCAN_NB>>>();
    scanC_kernel<<<SCAN_NB, 256>>>();
    fill_kernel<<<(EE + 255) / 256, 256>>>(ei_in);

    dim3 g2(2, (NN + 127) / 128), g1(1, (NN + 127) / 128);
    // ---- encoder (1xTF32) ----
    mma_gemm_kernel<1><<<g2, 256>>>(x, 128, whi, ew1, 256, dset, lin);
    agg_kernel<256, 1><<<(NN * 32 + 255) / 256, 256>>>(lin, eb1, hbuf);
    mma_gemm_kernel<0><<<g1, 256>>>(hbuf, 256, whi + WSZ, ew2, 128, nullptr, lin);
    agg_kernel<128, 0><<<(NN * 32 + 255) / 256, 256>>>(lin, eb2, zb);

    // ---- predictors + forward swaps ----
    ep1u_kernel<<<(NN + 31) / 32, 256>>>(zb, p1w1, p1b1, p1w2, p1b2, p2w1);
    fswap_kernel<<<1, 1>>>(plan);

    // ---- reverse process (swap fused into scores2 last block) ----
    for (int t = 0; t < TSTEPS; t++)
        scores2_kernel<<<(NN + 255) / 256, 256>>>(zb, p2w1, p2b1, p2w2, p2b2, rcoin[t]);

    // ---- final-graph CSR + dinv ----
    zero_cnt_kernel<<<(NN + 255) / 256, 256>>>();
    hist_kernel<<<(EE + 255) / 256, 256>>>(dev_ei + EE);
    scanA_kernel<<<SCAN_NB, 256>>>();
    scanB_kernel<<<1, SCAN_NB>>>();
    scanC_kernel<<<SCAN_NB, 256>>>();
    fill_kernel<<<(EE + 255) / 256, 256>>>(dev_ei);

    // ---- decoder (1xTF32) ----
    mma_gemm_kernel<1><<<g2, 256>>>(zb, 128, whi + 2 * WSZ, dw1, 256, dset, lin);
    agg_kernel<256, 1><<<(NN * 32 + 255) / 256, 256>>>(lin, db1, hbuf);
    mma_gemm_kernel<0><<<g1, 256>>>(hbuf, 256, whi + 3 * WSZ, dw2, 128, nullptr, lin);
    agg_kernel<128, 0><<<(NN * 32 + 255) / 256, 256>>>(lin, db2, out);

    // ---- emit final edge index as floats ----
    eiout_kernel<<<(2 * EE + 255) / 256, 256>>>(out);
}

// round 8
// speedup vs baseline: 2.3354x; 1.0317x over previous
#include <cuda_runtime.h>
#include <stdint.h>
#include <vector>
#include <algorithm>

#define NN 50000
#define EE 800000
#define FF 128
#define TSTEPS 5
#define SCAN_NB 128

// W offsets in g_Whi: enc1 192x256, enc2 256x128, dec1 192x256, dec2 256x128
#define W_ENC1 0
#define W_ENC2 49152
#define W_DEC1 81920
#define W_DEC2 131072
#define W_TOT  163840

// ---------------- static device buffers ----------------
__device__ int   g_ei[2 * EE];
__device__ int   g_cnt[NN];
__device__ int   g_rowptr[NN + 1];
__device__ int   g_cursor[NN];
__device__ int   g_csr[EE];
__device__ int   g_bsum[SCAN_NB];
__device__ int   g_done;
__device__ int   g_bar;
__device__ int   g_barfin;
__device__ float g_dinv[NN];
__device__ float g_lin[(size_t)NN * 256];
__device__ float g_hbuf[(size_t)NN * 256];
__device__ float g_z[(size_t)NN * 128];
__device__ float g_Ut[(size_t)64 * NN];
__device__ float g_Whi[W_TOT];
__device__ unsigned long long g_amax[2];

struct FwdPlan { int i1[TSTEPS]; int i2[TSTEPS]; int coin[TSTEPS]; };

__device__ __forceinline__ float tf32rna(float x) {
    uint32_t u; asm("cvt.rna.tf32.f32 %0, %1;" : "=r"(u) : "f"(x));
    return __uint_as_float(u);
}
__device__ __forceinline__ unsigned long long packmax(float v, int idx) {
    unsigned u = __float_as_uint(v);
    u ^= ((unsigned)((int)u >> 31)) | 0x80000000u;
    return ((unsigned long long)u << 32) | (unsigned)(0xFFFFFFFFu - (unsigned)idx);
}
__device__ __forceinline__ int unpack_idx(unsigned long long k) {
    return (int)(0xFFFFFFFFu - (unsigned)(k & 0xFFFFFFFFu));
}
// swap + incremental in-degree count maintenance
__device__ __forceinline__ void do_swap(int i1, int i2, int coin) {
    int a = g_ei[i1], b = g_ei[EE + i1];
    int c = g_ei[i2], d = g_ei[EE + i2];
    int n10, n11, n20, n21;
    if (coin) { n10 = a; n11 = d; n20 = c; n21 = b; }
    else      { n10 = a; n11 = c; n20 = b; n21 = d; }
    g_ei[i1] = n10; g_ei[EE + i1] = n11;
    g_ei[i2] = n20; g_ei[EE + i2] = n21;
    if (i1 == i2) {   // slot written twice; final = (n20, n21)
        if (n21 != b) { atomicSub(&g_cnt[b], 1); atomicAdd(&g_cnt[n21], 1); }
    } else {
        if (n11 != b) { atomicSub(&g_cnt[b], 1); atomicAdd(&g_cnt[n11], 1); }
        if (n21 != d) { atomicSub(&g_cnt[d], 1); atomicAdd(&g_cnt[n21], 1); }
    }
}

// ---------------- init: W tf32 rounding + cnt zero + flags ----------------
__global__ void init_kernel(const float* __restrict__ ew1, const float* __restrict__ ew2,
                            const float* __restrict__ dw1, const float* __restrict__ dw2) {
    int i = blockIdx.x * blockDim.x + threadIdx.x;
    if (i < W_TOT) {
        const float* src; int off;
        if (i < W_ENC2)      { src = ew1; off = i; }
        else if (i < W_DEC1) { src = ew2; off = i - W_ENC2; }
        else if (i < W_DEC2) { src = dw1; off = i - W_DEC1; }
        else                 { src = dw2; off = i - W_DEC2; }
        g_Whi[i] = tf32rna(src[off]);
    }
    if (i < NN) g_cnt[i] = 0;
    if (i == 0) {
        g_amax[0] = 0ULL; g_amax[1] = 0ULL;
        g_done = 0; g_bar = 0; g_barfin = 0;
    }
}

// copy ei into g_ei AND histogram dst half in the same pass
__global__ void copyhist_kernel(const int* __restrict__ ei) {
    int i = blockIdx.x * blockDim.x + threadIdx.x;
    if (i < 2 * EE) {
        int v = ei[i];
        g_ei[i] = v;
        if (i >= EE) atomicAdd(&g_cnt[v], 1);
    }
}

// ---------------- fused scan (single launch, grid barrier; 128 blocks co-resident) ----------------
__global__ void __launch_bounds__(256) scan_fused() {
    const int CH = (NN + SCAN_NB - 1) / SCAN_NB;   // 391
    const int TC = 2;
    int b = blockIdx.x, t = threadIdx.x;
    int beg = b * CH;
    int c[TC]; int s = 0;
#pragma unroll
    for (int i = 0; i < TC; i++) {
        int n = beg + t * TC + i;
        c[i] = (n < beg + CH && n < NN) ? g_cnt[n] : 0;
        s += c[i];
    }
    // block-wide inclusive scan of s
    int x = s;
    for (int o = 1; o < 32; o <<= 1) {
        int y = __shfl_up_sync(~0u, x, o);
        if ((t & 31) >= o) x += y;
    }
    __shared__ int ws[8];
    __shared__ int spre;
    if ((t & 31) == 31) ws[t >> 5] = x;
    __syncthreads();
    int add = 0;
#pragma unroll
    for (int wI = 0; wI < 8; wI++) if (wI < (t >> 5)) add += ws[wI];
    if (t == 0) {
        int tot = 0;
#pragma unroll
        for (int wI = 0; wI < 8; wI++) tot += ws[wI];
        g_bsum[b] = tot;
        __threadfence();
        atomicAdd(&g_bar, 1);
        while (*(volatile int*)&g_bar < SCAN_NB) __nanosleep(32);
    }
    __syncthreads();
    __threadfence();
    // exclusive prefix of block sums for this block
    {
        int v = (t < b) ? *((volatile int*)&g_bsum[t]) : 0;
        for (int o = 16; o; o >>= 1) v += __shfl_down_sync(~0u, v, o);
        if ((t & 31) == 0) ws[t >> 5] = v;
        __syncthreads();
        if (t == 0) {
            int p = 0;
#pragma unroll
            for (int wI = 0; wI < 8; wI++) p += ws[wI];
            spre = p;
        }
        __syncthreads();
    }
    int run = spre + (x + add - s);
#pragma unroll
    for (int i = 0; i < TC; i++) {
        int n = beg + t * TC + i;
        if (n < beg + CH && n < NN) {
            g_rowptr[n] = run; g_cursor[n] = run;
            float df = (float)(c[i] + 1);
            float r = rsqrtf(df);
            r = r * (1.5f - 0.5f * df * r * r);
            g_dinv[n] = r;
            run += c[i];
        }
    }
    if (b == 0 && t == 0) g_rowptr[NN] = EE;
    __syncthreads();
    if (t == 0) {
        int v = atomicAdd(&g_barfin, 1);
        if (v == SCAN_NB - 1) { g_bar = 0; g_barfin = 0; }
    }
}

__global__ void fill_kernel(const int* __restrict__ ei) {
    int e = blockIdx.x * blockDim.x + threadIdx.x;
    if (e < EE) {
        int s = ei[e], d = ei[EE + e];
        int pos = atomicAdd(&g_cursor[d], 1);
        g_csr[pos] = s;
    }
}
// final fill: also writes the edge-index output floats
__global__ void fillout_kernel(float* __restrict__ out) {
    int e = blockIdx.x * blockDim.x + threadIdx.x;
    if (e < EE) {
        int s = g_ei[e], d = g_ei[EE + e];
        int pos = atomicAdd(&g_cursor[d], 1);
        g_csr[pos] = s;
        out[(size_t)NN * FF + e] = (float)s;
        out[(size_t)NN * FF + EE + e] = (float)d;
    }
}

// ---------------- layer-1 aggregation (input side, one-hot on the fly) ----------------
// y[n][0:128]  = dinv[n]*(x[n]*dinv[n] + sum_src x[src]*dinv[src])
// y[n][128+d]  = dinv[n]*(dinv[n]*[dset[n]==d] + sum_src dinv[src]*[dset[src]==d])
__global__ void aggx_kernel(const float* __restrict__ x, const int* __restrict__ dset,
                            float* __restrict__ y) {
    int warp = (blockIdx.x * blockDim.x + threadIdx.x) >> 5;
    int lane = threadIdx.x & 31;
    if (warp >= NN) return;
    int n = warp;
    float dvn = g_dinv[n];
    const float4* x4 = (const float4*)x;
    float4 a = x4[(size_t)n * 32 + lane];
    a.x *= dvn; a.y *= dvn; a.z *= dvn; a.w *= dvn;
    float oh0 = 0.f, oh1 = 0.f, oh2 = 0.f, oh3 = 0.f;
    int dn = dset[n];
    if ((dn >> 2) == lane) {
        int q = dn & 3;
        if (q == 0) oh0 += dvn; else if (q == 1) oh1 += dvn;
        else if (q == 2) oh2 += dvn; else oh3 += dvn;
    }
    int beg = g_rowptr[n], end = g_rowptr[n + 1];
    for (int p = beg; p < end; ++p) {
        int s = g_csr[p];
        float ds = g_dinv[s];
        float4 bx = x4[(size_t)s * 32 + lane];
        a.x += bx.x * ds; a.y += bx.y * ds; a.z += bx.z * ds; a.w += bx.w * ds;
        int dsrc = dset[s];
        if ((dsrc >> 2) == lane) {
            int q = dsrc & 3;
            if (q == 0) oh0 += ds; else if (q == 1) oh1 += ds;
            else if (q == 2) oh2 += ds; else oh3 += ds;
        }
    }
    a.x *= dvn; a.y *= dvn; a.z *= dvn; a.w *= dvn;
    float4* y4 = (float4*)(y + (size_t)n * 192);
    y4[lane] = a;
    if (lane < 16)
        y4[32 + lane] = make_float4(oh0 * dvn, oh1 * dvn, oh2 * dvn, oh3 * dvn);
}

// ---------------- tensor-core GEMM (1xTF32) ----------------
// EPI=0: out = acc*dinv[m] ; EPI=1: out = relu(acc + bias[c])
__device__ __forceinline__ void mma8(float d[4], const uint32_t a[4], const uint32_t b[2]) {
    asm("mma.sync.aligned.m16n8k8.row.col.f32.tf32.tf32.f32 "
        "{%0,%1,%2,%3}, {%4,%5,%6,%7}, {%8,%9}, {%0,%1,%2,%3};"
        : "+f"(d[0]), "+f"(d[1]), "+f"(d[2]), "+f"(d[3])
        : "r"(a[0]), "r"(a[1]), "r"(a[2]), "r"(a[3]), "r"(b[0]), "r"(b[1]));
}

template <int EPI>
__global__ void __launch_bounds__(256) mma_gemm_kernel(
    const float* __restrict__ A, int K,
    const float* __restrict__ Whi, const float* __restrict__ bias, int C,
    float* __restrict__ out) {
    const int SA = 20;
    const int SB = 136;
    __shared__ float Ahi[128 * SA];
    __shared__ float Bhi[16 * SB];
    int bm = blockIdx.y * 128, bn = blockIdx.x * 128;
    int tid = threadIdx.x, lane = tid & 31, w = tid >> 5;
    int wm = w >> 1, wn = w & 1;

    float acc[2][8][4];
#pragma unroll
    for (int mt = 0; mt < 2; mt++)
#pragma unroll
        for (int nt = 0; nt < 8; nt++)
#pragma unroll
            for (int r = 0; r < 4; r++) acc[mt][nt][r] = 0.f;

    for (int kt = 0; kt < K; kt += 16) {
#pragma unroll
        for (int it = 0; it < 2; it++) {
            int f = tid + it * 256;
            int m = f >> 2, k4 = (f & 3) << 2;
            float4 v = make_float4(0.f, 0.f, 0.f, 0.f);
            if (bm + m < NN) v = *(const float4*)&A[(size_t)(bm + m) * K + kt + k4];
            int o = m * SA + k4;
            Ahi[o] = tf32rna(v.x); Ahi[o + 1] = tf32rna(v.y);
            Ahi[o + 2] = tf32rna(v.z); Ahi[o + 3] = tf32rna(v.w);
        }
#pragma unroll
        for (int it = 0; it < 2; it++) {
            int f = tid + it * 256;
            int k = f >> 5, n4 = (f & 31) << 2;
            float4 v = *(const float4*)&Whi[(size_t)(kt + k) * C + bn + n4];
            *(float4*)&Bhi[k * SB + n4] = v;
        }
        __syncthreads();
#pragma unroll
        for (int kk = 0; kk < 16; kk += 8) {
            uint32_t ah[2][4];
#pragma unroll
            for (int mt = 0; mt < 2; mt++) {
                int mr = wm * 32 + mt * 16 + (lane >> 2);
                int kc = kk + (lane & 3);
                ah[mt][0] = __float_as_uint(Ahi[mr * SA + kc]);
                ah[mt][1] = __float_as_uint(Ahi[(mr + 8) * SA + kc]);
                ah[mt][2] = __float_as_uint(Ahi[mr * SA + kc + 4]);
                ah[mt][3] = __float_as_uint(Ahi[(mr + 8) * SA + kc + 4]);
            }
#pragma unroll
            for (int nt = 0; nt < 8; nt++) {
                int nc = wn * 64 + nt * 8 + (lane >> 2);
                int kr = kk + (lane & 3);
                uint32_t bh[2] = { __float_as_uint(Bhi[kr * SB + nc]),
                                   __float_as_uint(Bhi[(kr + 4) * SB + nc]) };
#pragma unroll
                for (int mt = 0; mt < 2; mt++) mma8(acc[mt][nt], ah[mt], bh);
            }
        }
        __syncthreads();
    }
#pragma unroll
    for (int mt = 0; mt < 2; mt++)
#pragma unroll
        for (int rr = 0; rr < 2; rr++) {
            int row = bm + wm * 32 + mt * 16 + (lane >> 2) + rr * 8;
            if (row < NN) {
                float dv = (EPI == 0) ? g_dinv[row] : 0.f;
#pragma unroll
                for (int nt = 0; nt < 8; nt++) {
                    int col = wn * 64 + nt * 8 + (lane & 3) * 2;
                    float v0 = acc[mt][nt][rr * 2 + 0];
                    float v1 = acc[mt][nt][rr * 2 + 1];
                    if (EPI == 0) { v0 *= dv; v1 *= dv; }
                    else {
                        v0 = fmaxf(v0 + bias[bn + col], 0.f);
                        v1 = fmaxf(v1 + bias[bn + col + 1], 0.f);
                    }
                    *(float2*)&out[(size_t)row * C + bn + col] = make_float2(v0, v1);
                }
            }
        }
}

// ---------------- layer-2 aggregation (128-wide): out[n] = dinv[n]*(g[n]+sum)+bias ----------------
__global__ void agg_kernel(const float* __restrict__ g, const float* __restrict__ bias,
                           float* __restrict__ out) {
    int warp = (blockIdx.x * blockDim.x + threadIdx.x) >> 5;
    int lane = threadIdx.x & 31;
    if (warp >= NN) return;
    int n = warp;
    const float4* g4 = (const float4*)g;
    float4 a = g4[(size_t)n * 32 + lane];
    int beg = g_rowptr[n], end = g_rowptr[n + 1];
    for (int p = beg; p < end; ++p) {
        int s = g_csr[p];
        float4 b0 = g4[(size_t)s * 32 + lane];
        a.x += b0.x; a.y += b0.y; a.z += b0.z; a.w += b0.w;
    }
    float dv = g_dinv[n];
    float4 bb = ((const float4*)bias)[lane];
    a.x = a.x * dv + bb.x; a.y = a.y * dv + bb.y;
    a.z = a.z * dv + bb.z; a.w = a.w * dv + bb.w;
    ((float4*)out)[(size_t)n * 32 + lane] = a;
}

// ---------------- fused ep1 + U precompute ----------------
__global__ void __launch_bounds__(256) ep1u_kernel(
    const float* __restrict__ z,
    const float* __restrict__ p1w1, const float* __restrict__ p1b1,
    const float* __restrict__ p1w2, const float* __restrict__ p1b2,
    const float* __restrict__ p2w1) {
    __shared__ float zs[32][128];
    __shared__ float sm2[64][33];
    int tid = threadIdx.x;
    int grp = tid >> 6, k = tid & 63;
    int n0 = blockIdx.x * 32;
    for (int i = tid; i < 32 * 128; i += 256) {
        int gi = n0 * 128 + i;
        ((float*)zs)[i] = (gi < NN * 128) ? z[gi] : 0.f;
    }
    __syncthreads();
    float bk = p1b1[k];
    float acc1[8], accu[8];
#pragma unroll
    for (int nn = 0; nn < 8; nn++) { acc1[nn] = bk; accu[nn] = 0.f; }
#pragma unroll 4
    for (int j = 0; j < 128; j++) {
        float w1v = p1w1[j * 64 + k];
        float w2v = p2w1[j * 64 + k];
#pragma unroll
        for (int nn = 0; nn < 8; nn++) {
            float zv = zs[grp * 8 + nn][j];
            acc1[nn] += zv * w1v;
            accu[nn] += zv * w2v;
        }
    }
    float wk = p1w2[k];
#pragma unroll
    for (int nn = 0; nn < 8; nn++) sm2[k][grp * 8 + nn] = fmaxf(acc1[nn], 0.f) * wk;
    __syncthreads();
    {
        int nd = tid >> 3, q = tid & 7;
        float s = 0.f;
#pragma unroll
        for (int m = 0; m < 8; m++) s += sm2[q * 8 + m][nd];
        for (int o = 4; o; o >>= 1) s += __shfl_down_sync(~0u, s, o, 8);
        if (q == 0 && n0 + nd < NN) atomicMax(&g_amax[0], packmax(s + p1b2[0], n0 + nd));
    }
    __syncthreads();
#pragma unroll
    for (int nn = 0; nn < 8; nn++) sm2[k][grp * 8 + nn] = accu[nn];
    __syncthreads();
    for (int i = tid; i < 64 * 32; i += 256) {
        int row = i >> 5, col = i & 31;
        if (n0 + col < NN) g_Ut[(size_t)row * NN + n0 + col] = sm2[row][col];
    }
}

__global__ void fswap_kernel(FwdPlan p) {
    for (int t = 0; t < TSTEPS; t++) do_swap(p.i1[t], p.i2[t], p.coin[t]);
}

// scores2 + fused c + fused swap (last block)
__global__ void scores2_kernel(const float* __restrict__ z, const float* __restrict__ w1,
                               const float* __restrict__ b1, const float* __restrict__ w2,
                               const float* __restrict__ b2, int coin) {
    __shared__ float z01[256];
    __shared__ float cs[64], ws[64];
    __shared__ unsigned long long red[256];
    int tid = threadIdx.x;
    int i1 = unpack_idx(g_amax[0]);
    int e10 = g_ei[i1], e11 = g_ei[EE + i1];
    if (tid < 128) z01[tid] = z[(size_t)e10 * 128 + tid];
    else           z01[tid] = z[(size_t)e11 * 128 + (tid - 128)];
    __syncthreads();
    if (tid < 64) {
        float c = b1[tid];
#pragma unroll 8
        for (int j = 0; j < 256; j++) c += z01[j] * w1[(size_t)(128 + j) * 64 + tid];
        cs[tid] = c; ws[tid] = w2[tid];
    }
    __syncthreads();
    int n = blockIdx.x * 256 + tid;
    unsigned long long key = 0ULL;
    if (n < NN) {
        float s = b2[0];
#pragma unroll
        for (int k = 0; k < 64; k++) {
            float u = g_Ut[(size_t)k * NN + n] + cs[k];
            s += fmaxf(u, 0.f) * ws[k];
        }
        key = packmax(s, n);
    }
    red[tid] = key;
    __syncthreads();
    for (int off = 128; off; off >>= 1) {
        if (tid < off) { unsigned long long o = red[tid + off]; if (o > red[tid]) red[tid] = o; }
        __syncthreads();
    }
    if (tid == 0) {
        atomicMax(&g_amax[1], red[0]);
        __threadfence();
        int t = atomicAdd(&g_done, 1);
        if (t == (int)gridDim.x - 1) {
            g_done = 0;
            int a = unpack_idx(g_amax[0]);
            int b = unpack_idx(g_amax[1]);
            do_swap(a, b, coin);
            g_amax[1] = 0ULL;
        }
    }
}

// ---------------- host-side JAX threefry (partitionable semantics) ----------------
static inline uint32_t rotl32(uint32_t x, int d) { return (x << d) | (x >> (32 - d)); }
static void tf2x32(uint32_t k0, uint32_t k1, uint32_t x0, uint32_t x1,
                   uint32_t& o0, uint32_t& o1) {
    uint32_t ks2 = k0 ^ k1 ^ 0x1BD11BDAu;
    static const int RA[4] = {13, 15, 26, 6}, RB[4] = {17, 29, 16, 24};
    x0 += k0; x1 += k1;
#define RND4(R) for (int i = 0; i < 4; i++) { x0 += x1; x1 = rotl32(x1, R[i]); x1 ^= x0; }
    RND4(RA) x0 += k1;  x1 += ks2 + 1;
    RND4(RB) x0 += ks2; x1 += k0 + 2;
    RND4(RA) x0 += k0;  x1 += k1 + 3;
    RND4(RB) x0 += k1;  x1 += ks2 + 4;
    RND4(RA) x0 += ks2; x1 += k0 + 5;
#undef RND4
    o0 = x0; o1 = x1;
}
struct KP { uint32_t a, b; };
static KP kfold(KP k, uint32_t t) { KP r; tf2x32(k.a, k.b, 0u, t, r.a, r.b); return r; }
static void ksplit(KP k, KP& A, KP& B) {
    tf2x32(k.a, k.b, 0u, 0u, A.a, A.b);
    tf2x32(k.a, k.b, 0u, 1u, B.a, B.b);
}
static inline uint32_t kbits(KP k, uint32_t i) {
    uint32_t o0, o1; tf2x32(k.a, k.b, 0u, i, o0, o1); return o0 ^ o1;
}
static bool kbern(KP k) { return (kbits(k, 0u) >> 31) == 0; }

static void perm_first2(KP key, int& i1, int& i2) {
    KP kA, s1, kB, s2;
    ksplit(key, kA, s1);
    ksplit(kA, kB, s2);
    std::vector<uint32_t> b1(EE), b2(EE);
    for (int i = 0; i < EE; i++) b1[i] = kbits(s1, (uint32_t)i);
    for (int i = 0; i < EE; i++) b2[i] = kbits(s2, (uint32_t)i);
    uint64_t m0 = ~0ULL, m1 = ~0ULL;
    for (int p = 0; p < EE; p++) {
        uint64_t v = ((uint64_t)b2[p] << 32) | (uint32_t)p;
        if (v < m0) { m1 = m0; m0 = v; }
        else if (v < m1) { m1 = v; }
    }
    int p0 = (int)(uint32_t)(m0 & 0xFFFFFFFFu);
    int p1 = (int)(uint32_t)(m1 & 0xFFFFFFFFu);
    std::vector<uint64_t> s(EE);
    for (int j = 0; j < EE; j++) s[j] = ((uint64_t)b1[j] << 32) | (uint32_t)j;
    std::nth_element(s.begin(), s.begin() + p0, s.end());
    i1 = (int)(uint32_t)(s[p0] & 0xFFFFFFFFu);
    std::nth_element(s.begin(), s.begin() + p1, s.end());
    i2 = (int)(uint32_t)(s[p1] & 0xFFFFFFFFu);
}

extern "C" void kernel_launch(void* const* d_in, const int* in_sizes, int n_in,
                              void* d_out, int out_size) {
    int base = n_in - 16;
    const float* x    = (const float*)d_in[0];
    const int* ei_in  = (const int*)d_in[1];
    const int* dset   = (const int*)d_in[2];
    const float* ew1  = (const float*)d_in[base + 0];
    const float* eb1  = (const float*)d_in[base + 1];
    const float* ew2  = (const float*)d_in[base + 2];
    const float* eb2  = (const float*)d_in[base + 3];
    const float* dw1  = (const float*)d_in[base + 4];
    const float* db1  = (const float*)d_in[base + 5];
    const float* dw2  = (const float*)d_in[base + 6];
    const float* db2  = (const float*)d_in[base + 7];
    const float* p1w1 = (const float*)d_in[base + 8];
    const float* p1b1 = (const float*)d_in[base + 9];
    const float* p1w2 = (const float*)d_in[base + 10];
    const float* p1b2 = (const float*)d_in[base + 11];
    const float* p2w1 = (const float*)d_in[base + 12];
    const float* p2b1 = (const float*)d_in[base + 13];
    const float* p2w2 = (const float*)d_in[base + 14];
    const float* p2b2 = (const float*)d_in[base + 15];
    float* out = (float*)d_out;

    // ---- host plan (pure PRNG constants, untimed) ----
    FwdPlan plan;
    int rcoin[TSTEPS];
    for (int t = 0; t < TSTEPS; t++) {
        KP kt = kfold({0u, 1u}, (uint32_t)t);
        KP k1, k2;
        ksplit(kt, k1, k2);
        plan.coin[t] = kbern(k2) ? 1 : 0;
        perm_first2(k1, plan.i1[t], plan.i2[t]);
        rcoin[t] = kbern(kfold({0u, 2u}, (uint32_t)t)) ? 1 : 0;
    }

    float* lin = nullptr; float* hbuf = nullptr; float* zb = nullptr; float* whi = nullptr;
    cudaGetSymbolAddress((void**)&lin, g_lin);
    cudaGetSymbolAddress((void**)&hbuf, g_hbuf);
    cudaGetSymbolAddress((void**)&zb, g_z);
    cudaGetSymbolAddress((void**)&whi, g_Whi);

    dim3 g2(2, (NN + 127) / 128), g1(1, (NN + 127) / 128);
    int agrid = (NN * 32 + 255) / 256;

    // ---- init + original-graph CSR ----
    init_kernel<<<(W_TOT + 255) / 256, 256>>>(ew1, ew2, dw1, dw2);
    copyhist_kernel<<<(2 * EE + 255) / 256, 256>>>(ei_in);
    scan_fused<<<SCAN_NB, 256>>>();
    fill_kernel<<<(EE + 255) / 256, 256>>>(ei_in);

    // ---- encoder (agg-first layer 1) ----
    aggx_kernel<<<agrid, 256>>>(x, dset, hbuf);
    mma_gemm_kernel<1><<<g2, 256>>>(hbuf, 192, whi + W_ENC1, eb1, 256, lin);
    mma_gemm_kernel<0><<<g1, 256>>>(lin, 256, whi + W_ENC2, nullptr, 128, hbuf);
    agg_kernel<<<agrid, 256>>>(hbuf, eb2, zb);

    // ---- predictors + forward swaps ----
    ep1u_kernel<<<(NN + 31) / 32, 256>>>(zb, p1w1, p1b1, p1w2, p1b2, p2w1);
    fswap_kernel<<<1, 1>>>(plan);

    // ---- reverse process ----
    for (int t = 0; t < TSTEPS; t++)
        scores2_kernel<<<(NN + 255) / 256, 256>>>(zb, p2w1, p2b1, p2w2, p2b2, rcoin[t]);

    // ---- final-graph CSR (counts maintained incrementally by swaps) ----
    scan_fused<<<SCAN_NB, 256>>>();
    fillout_kernel<<<(EE + 255) / 256, 256>>>(out);

    // ---- decoder (agg-first layer 1) ----
    aggx_kernel<<<agrid, 256>>>(zb, dset, hbuf);
    mma_gemm_kernel<1><<<g2, 256>>>(hbuf, 192, whi + W_DEC1, db1, 256, lin);
    mma_gemm_kernel<0><<<g1, 256>>>(lin, 256, whi + W_DEC2, nullptr, 128, hbuf);
    agg_kernel<<<agrid, 256>>>(hbuf, db2, out);
}